// round 14
// baseline (speedup 1.0000x reference)
#include <cuda_runtime.h>
#include <cuda_bf16.h>
#include <math.h>

#define N_TOK   16384
#define D_MODEL 2048
#define Q_DIM   512
#define H_HEADS 4
#define HQ      2048      // H * Q
#define HALF    256       // Q/2
#define S_KEYS  256
#define TOPK    4
#define BN_EPS  1e-5f
#define NEG_BIG (-1e30f)
#define NPART   4
#define CHUNK   (N_TOK / NPART)
#define DELTA   1e-4f     // suspicion margin (>> mma-path noise)

typedef unsigned long long u64;
typedef unsigned int u32;

// -------------------- device scratch (static, no allocation) --------------------
static __device__ float  g_q [(size_t)N_TOK * HQ];
static __device__ float  g_s [(size_t)N_TOK * HQ];
static __device__ float  g_pm[NPART][HQ];
static __device__ float  g_pv[NPART][HQ];
static __device__ float  g_mun[HQ];
static __device__ float  g_rn [HQ];
static __device__ float  g_Kt [2 * HALF * S_KEYS];
static __device__ int    g_cnt;
static __device__ int    g_list[N_TOK * H_HEADS];
// bf16 3-way splits of x (A) and transposed Wq (B, [h*512+n][k])
static __device__ __align__(16) __nv_bfloat16 g_xs1[(size_t)N_TOK * D_MODEL];
static __device__ __align__(16) __nv_bfloat16 g_xs2[(size_t)N_TOK * D_MODEL];
static __device__ __align__(16) __nv_bfloat16 g_xs3[(size_t)N_TOK * D_MODEL];
static __device__ __align__(16) __nv_bfloat16 g_ws1[(size_t)HQ * D_MODEL];
static __device__ __align__(16) __nv_bfloat16 g_ws2[(size_t)HQ * D_MODEL];
static __device__ __align__(16) __nv_bfloat16 g_ws3[(size_t)HQ * D_MODEL];

// -------------------- helpers --------------------
__device__ __forceinline__ u64 f2_pack(float lo, float hi) {
    u64 r; asm("mov.b64 %0, {%1, %2};" : "=l"(r) : "f"(lo), "f"(hi)); return r;
}
__device__ __forceinline__ void f2_unpack(u64 v, float& lo, float& hi) {
    asm("mov.b64 {%0, %1}, %2;" : "=f"(lo), "=f"(hi) : "l"(v));
}
__device__ __forceinline__ u64 f2_fma(u64 a, u64 b, u64 c) {
    u64 d; asm("fma.rn.f32x2 %0, %1, %2, %3;" : "=l"(d) : "l"(a), "l"(b), "l"(c)); return d;
}
__device__ __forceinline__ void mma_bf16(float* d, const u32* a, const u32* b) {
    asm volatile(
        "mma.sync.aligned.m16n8k16.row.col.f32.bf16.bf16.f32 "
        "{%0,%1,%2,%3}, {%4,%5,%6,%7}, {%8,%9}, {%0,%1,%2,%3};"
        : "+f"(d[0]), "+f"(d[1]), "+f"(d[2]), "+f"(d[3])
        : "r"(a[0]), "r"(a[1]), "r"(a[2]), "r"(a[3]), "r"(b[0]), "r"(b[1]));
}

// =====================================================================
// Split kernels
// =====================================================================
__device__ __forceinline__ void split3(float v, __nv_bfloat16& b1, __nv_bfloat16& b2, __nv_bfloat16& b3) {
    b1 = __float2bfloat16_rn(v);
    float r1 = v - __bfloat162float(b1);
    b2 = __float2bfloat16_rn(r1);
    float r2 = r1 - __bfloat162float(b2);
    b3 = __float2bfloat16_rn(r2);
}

__global__ __launch_bounds__(256) void k_split_x(const float* __restrict__ x)
{
    size_t i0 = ((size_t)blockIdx.x * 256 + threadIdx.x) * 4;
    float4 v = *(const float4*)(x + i0);
    float vv[4] = {v.x, v.y, v.z, v.w};
    #pragma unroll
    for (int u = 0; u < 4; u++) {
        __nv_bfloat16 b1, b2, b3;
        split3(vv[u], b1, b2, b3);
        g_xs1[i0 + u] = b1; g_xs2[i0 + u] = b2; g_xs3[i0 + u] = b3;
    }
}

__global__ void k_split_w(const float* __restrict__ Wq)
{
    __shared__ float tile[32][33];
    int k0 = blockIdx.x * 32, n0 = blockIdx.y * 32, h = blockIdx.z;
    int tx = threadIdx.x, ty = threadIdx.y;
    #pragma unroll
    for (int q = 0; q < 4; q++) {
        int r = ty + q * 8;
        tile[r][tx] = Wq[(size_t)h * D_MODEL * Q_DIM + (size_t)(k0 + r) * Q_DIM + n0 + tx];
    }
    __syncthreads();
    #pragma unroll
    for (int q = 0; q < 4; q++) {
        int nn = ty + q * 8;
        float v = tile[tx][nn];
        __nv_bfloat16 b1, b2, b3;
        split3(v, b1, b2, b3);
        size_t o = (size_t)(h * Q_DIM + n0 + nn) * D_MODEL + k0 + tx;
        g_ws1[o] = b1; g_ws2[o] = b2; g_ws3[o] = b3;
    }
}

// =====================================================================
// Kernel 1: q = x @ Wq + bq via mma.sync m16n8k16 bf16, 3-split/6-product.
// TWO accumulator groups: hi = s1*s1 (full magnitude, only 64 tile adds),
// lo = remaining 5 products (<=2^-9 scale). q = (hi + lo) + bias.
// Block 128x64, BK=32, 256 thr = 8 warps (4m x 2n), warp tile 32x32.
// =====================================================================
#define RSB     80
#define ASM_OFF(s) ((s) * 10240)                  // A: 128 rows * 80B
#define BSM_OFF(s) (30720 + (s) * 5120)           // B: 64 rows * 80B
#define SMEM_MMA 46080

__global__ __launch_bounds__(256, 1) void k_gemm_q_mma(const float* __restrict__ bq)
{
    extern __shared__ char smem[];
    const int tid  = threadIdx.x;
    const int wid  = tid >> 5, lane = tid & 31;
    const int m0   = (wid & 3) * 32;
    const int n0   = (wid >> 2) * 32;
    const int row0 = blockIdx.x * 128;
    const int col0 = blockIdx.y * 64;

    float dh[2][4][4], dl[2][4][4];
    #pragma unroll
    for (int mf = 0; mf < 2; mf++)
        #pragma unroll
        for (int nf = 0; nf < 4; nf++)
            #pragma unroll
            for (int e = 0; e < 4; e++) { dh[mf][nf][e] = 0.0f; dl[mf][nf][e] = 0.0f; }

    const int lr = lane >> 2;
    const int lk = (lane & 3) * 2;

    for (int kt = 0; kt < D_MODEL; kt += 32) {
        // A: 3 splits x 128x32 bf16 = 512 uint4 each; B: 3 x 64x32 = 256 uint4 each
        #pragma unroll
        for (int s = 0; s < 3; s++) {
            const __nv_bfloat16* X = (s == 0) ? g_xs1 : (s == 1) ? g_xs2 : g_xs3;
            const __nv_bfloat16* W = (s == 0) ? g_ws1 : (s == 1) ? g_ws2 : g_ws3;
            #pragma unroll
            for (int t = 0; t < 2; t++) {
                int id = tid + t * 256;
                int r  = id >> 2;
                int kk = (id & 3) * 8;
                *(uint4*)(smem + ASM_OFF(s) + r * RSB + kk * 2) =
                    *(const uint4*)(X + (size_t)(row0 + r) * D_MODEL + kt + kk);
            }
            {
                int r  = tid >> 2;
                int kk = (tid & 3) * 8;
                *(uint4*)(smem + BSM_OFF(s) + r * RSB + kk * 2) =
                    *(const uint4*)(W + (size_t)(col0 + r) * D_MODEL + kt + kk);
            }
        }
        __syncthreads();

        #pragma unroll
        for (int ks = 0; ks < 2; ks++) {
            const int kb = ks * 16 + lk;
            #pragma unroll
            for (int si = 0; si < 3; si++) {
                u32 a[2][4];
                #pragma unroll
                for (int mf = 0; mf < 2; mf++) {
                    const char* base = smem + ASM_OFF(si) + (size_t)(m0 + mf * 16 + lr) * RSB;
                    a[mf][0] = *(const u32*)(base + kb * 2);
                    a[mf][1] = *(const u32*)(base + 8 * RSB + kb * 2);
                    a[mf][2] = *(const u32*)(base + kb * 2 + 16);
                    a[mf][3] = *(const u32*)(base + 8 * RSB + kb * 2 + 16);
                }
                const int njmax = 3 - si;
                #pragma unroll
                for (int sj = 0; sj < 3; sj++) {
                    if (sj >= njmax) break;
                    #pragma unroll
                    for (int nf = 0; nf < 4; nf++) {
                        const char* bb = smem + BSM_OFF(sj) + (size_t)(n0 + nf * 8 + lr) * RSB;
                        u32 b[2];
                        b[0] = *(const u32*)(bb + kb * 2);
                        b[1] = *(const u32*)(bb + kb * 2 + 16);
                        if (si == 0 && sj == 0) {
                            mma_bf16(dh[0][nf], a[0], b);
                            mma_bf16(dh[1][nf], a[1], b);
                        } else {
                            mma_bf16(dl[0][nf], a[0], b);
                            mma_bf16(dl[1][nf], a[1], b);
                        }
                    }
                }
            }
        }
        __syncthreads();
    }

    #pragma unroll
    for (int mf = 0; mf < 2; mf++) {
        #pragma unroll
        for (int nf = 0; nf < 4; nf++) {
            int r = row0 + m0 + mf * 16 + lr;
            int c = col0 + n0 + nf * 8 + lk;
            g_q[(size_t)r * HQ + c]           = (dh[mf][nf][0] + dl[mf][nf][0]) + bq[c];
            g_q[(size_t)r * HQ + c + 1]       = (dh[mf][nf][1] + dl[mf][nf][1]) + bq[c + 1];
            g_q[(size_t)(r + 8) * HQ + c]     = (dh[mf][nf][2] + dl[mf][nf][2]) + bq[c];
            g_q[(size_t)(r + 8) * HQ + c + 1] = (dh[mf][nf][3] + dl[mf][nf][3]) + bq[c + 1];
        }
    }
}

// =====================================================================
// Stats (frozen recipe, MLP-8 loads).
// =====================================================================
__global__ __launch_bounds__(256) void k_mean_part()
{
    int c    = blockIdx.x * 8 + (threadIdx.x >> 5);
    int b    = blockIdx.y;
    int lane = threadIdx.x & 31;
    float s = 0.0f;
    const float* p = g_q + ((size_t)b * CHUNK + lane) * HQ + c;
    #pragma unroll 1
    for (int j = 0; j < CHUNK / 32; j += 8) {
        float v[8];
        #pragma unroll
        for (int u = 0; u < 8; u++) v[u] = p[(size_t)(j + u) * 32 * HQ];
        #pragma unroll
        for (int u = 0; u < 8; u++) s = __fadd_rn(s, v[u]);
    }
    #pragma unroll
    for (int off = 16; off > 0; off >>= 1)
        s = __fadd_rn(s, __shfl_down_sync(0xffffffffu, s, off));
    if (lane == 0) g_pm[b][c] = s;
}

__global__ __launch_bounds__(256) void k_mean_fin()
{
    int c = blockIdx.x * 256 + threadIdx.x;
    float s = g_pm[0][c];
    #pragma unroll
    for (int b = 1; b < NPART; b++) s = __fadd_rn(s, g_pm[b][c]);
    g_mun[c] = s * (1.0f / (float)N_TOK);
}

__global__ __launch_bounds__(256) void k_var_part()
{
    int c    = blockIdx.x * 8 + (threadIdx.x >> 5);
    int b    = blockIdx.y;
    int lane = threadIdx.x & 31;
    float mu = g_mun[c];
    float s = 0.0f;
    const float* p = g_q + ((size_t)b * CHUNK + lane) * HQ + c;
    #pragma unroll 1
    for (int j = 0; j < CHUNK / 32; j += 8) {
        float v[8];
        #pragma unroll
        for (int u = 0; u < 8; u++) v[u] = p[(size_t)(j + u) * 32 * HQ];
        #pragma unroll
        for (int u = 0; u < 8; u++) {
            float dd = __fsub_rn(v[u], mu);
            s = __fadd_rn(s, __fmul_rn(dd, dd));
        }
    }
    #pragma unroll
    for (int off = 16; off > 0; off >>= 1)
        s = __fadd_rn(s, __shfl_down_sync(0xffffffffu, s, off));
    if (lane == 0) g_pv[b][c] = s;
}

__global__ __launch_bounds__(256) void k_var_fin()
{
    int c = blockIdx.x * 256 + threadIdx.x;
    float s = g_pv[0][c];
    #pragma unroll
    for (int b = 1; b < NPART; b++) s = __fadd_rn(s, g_pv[b][c]);
    float var = s * (1.0f / (float)N_TOK);
    g_rn[c] = rsqrtf(__fadd_rn(var, BN_EPS));
}

__global__ __launch_bounds__(256) void k_transpose(
    const float* __restrict__ K1, const float* __restrict__ K2)
{
    int idx = blockIdx.x * 256 + threadIdx.x;
    int tbl = idx >> 16;
    int c   = (idx >> 8) & 255;
    int k   = idx & 255;
    const float* Ksrc = tbl ? K2 : K1;
    g_Kt[idx] = Ksrc[k * HALF + c];
}

// =====================================================================
// Kernel 4: scoring GEMM (frozen recipe) on mma-q.
// =====================================================================
__global__ __launch_bounds__(512) void k_gemm_s(
    const float* __restrict__ gamma, const float* __restrict__ beta)
{
    __shared__ float As[16][128];
    __shared__ float Bs[16][128];

    const int tid = threadIdx.x;
    const int tx  = tid & 15;
    const int ty  = tid >> 4;

    const int z   = blockIdx.z;
    const int tbl = z >> 2;
    const int h   = z & 3;
    const int cb  = h * Q_DIM + tbl * HALF;

    const float* A  = g_q + (size_t)blockIdx.x * 128 * HQ + cb;
    const float* B  = g_Kt + (size_t)tbl * HALF * S_KEYS + blockIdx.y * 128;
    const float* mu = g_mun + cb;
    const float* rn = g_rn  + cb;
    const float* gm = gamma + cb;
    const float* bt = beta  + cb;

    u64 acc2[4][4];
    #pragma unroll
    for (int i = 0; i < 4; i++)
        #pragma unroll
        for (int m = 0; m < 4; m++) acc2[i][m] = 0ull;

    const int ar = tid >> 2;
    const int ac = (tid & 3) * 4;
    const int br = tid >> 5;
    const int bc = (tid & 31) * 4;

    for (int kt = 0; kt < HALF; kt += 16) {
        float4 va = *(const float4*)(A + (size_t)ar * HQ + kt + ac);
        int c0 = kt + ac;
        va.x = __fmul_rn(__fsub_rn(va.x, mu[c0 + 0]), rn[c0 + 0]) * gm[c0 + 0] + bt[c0 + 0];
        va.y = __fmul_rn(__fsub_rn(va.y, mu[c0 + 1]), rn[c0 + 1]) * gm[c0 + 1] + bt[c0 + 1];
        va.z = __fmul_rn(__fsub_rn(va.z, mu[c0 + 2]), rn[c0 + 2]) * gm[c0 + 2] + bt[c0 + 2];
        va.w = __fmul_rn(__fsub_rn(va.w, mu[c0 + 3]), rn[c0 + 3]) * gm[c0 + 3] + bt[c0 + 3];
        As[ac + 0][ar] = va.x; As[ac + 1][ar] = va.y;
        As[ac + 2][ar] = va.z; As[ac + 3][ar] = va.w;
        *(float4*)(&Bs[br][bc]) = *(const float4*)(B + (size_t)(kt + br) * S_KEYS + bc);
        __syncthreads();

        #pragma unroll
        for (int k = 0; k < 16; k++) {
            u64 a2[4], b2[4];
            #pragma unroll
            for (int i = 0; i < 4; i++) {
                float av = As[k][ty * 4 + i];
                a2[i] = f2_pack(av, av);
            }
            #pragma unroll
            for (int m = 0; m < 4; m++)
                b2[m] = *(const u64*)(&Bs[k][tx * 8 + m * 2]);
            #pragma unroll
            for (int i = 0; i < 4; i++)
                #pragma unroll
                for (int m = 0; m < 4; m++)
                    acc2[i][m] = f2_fma(a2[i], b2[m], acc2[i][m]);
        }
        __syncthreads();
    }

    float* C = g_s + (size_t)blockIdx.x * 128 * HQ + cb + blockIdx.y * 128;
    #pragma unroll
    for (int i = 0; i < 4; i++) {
        int r = ty * 4 + i;
        #pragma unroll
        for (int m = 0; m < 4; m++) {
            float lo, hi;
            f2_unpack(acc2[i][m], lo, hi);
            int c = tx * 8 + m * 2;
            C[(size_t)r * HQ + c + 0] = lo;
            C[(size_t)r * HQ + c + 1] = hi;
        }
    }
}

// =====================================================================
// Shared top-k device function (frozen algorithm).
// flag=true: also compute min decision margin and append to list.
// =====================================================================
__device__ __forceinline__ void topk_row(int gw, int lane, float* out, bool flag)
{
    int n = gw >> 2;
    int h = gw & 3;

    const float* s1 = g_s + (size_t)n * HQ + h * Q_DIM;
    const float* s2 = s1 + HALF;

    float v1[8], v2[8];
    #pragma unroll
    for (int t = 0; t < 8; t++) { v1[t] = s1[t * 32 + lane]; v2[t] = s2[t * 32 + lane]; }

    float tv1[8], tv2[8];
    int   ti1[8], ti2[8];

    #pragma unroll
    for (int it = 0; it < 8; it++) {
        float bm = NEG_BIG; int bi = 0x7fffffff;
        #pragma unroll
        for (int t = 0; t < 8; t++)
            if (v1[t] > bm) { bm = v1[t]; bi = t * 32 + lane; }
        #pragma unroll
        for (int off = 16; off > 0; off >>= 1) {
            float om = __shfl_xor_sync(0xffffffffu, bm, off);
            int   oi = __shfl_xor_sync(0xffffffffu, bi, off);
            if (om > bm || (om == bm && oi < bi)) { bm = om; bi = oi; }
        }
        tv1[it] = bm; ti1[it] = bi;
        if ((bi & 31) == lane) v1[bi >> 5] = NEG_BIG;
    }
    #pragma unroll
    for (int it = 0; it < 8; it++) {
        float bm = NEG_BIG; int bi = 0x7fffffff;
        #pragma unroll
        for (int t = 0; t < 8; t++)
            if (v2[t] > bm) { bm = v2[t]; bi = t * 32 + lane; }
        #pragma unroll
        for (int off = 16; off > 0; off >>= 1) {
            float om = __shfl_xor_sync(0xffffffffu, bm, off);
            int   oi = __shfl_xor_sync(0xffffffffu, bi, off);
            if (om > bm || (om == bm && oi < bi)) { bm = om; bi = oi; }
        }
        tv2[it] = bm; ti2[it] = bi;
        if ((bi & 31) == lane) v2[bi >> 5] = NEG_BIG;
    }

    float v9a = NEG_BIG, v9b = NEG_BIG;
    if (flag) {
        #pragma unroll
        for (int t = 0; t < 8; t++) { v9a = fmaxf(v9a, v1[t]); v9b = fmaxf(v9b, v2[t]); }
        #pragma unroll
        for (int off = 16; off > 0; off >>= 1) {
            v9a = fmaxf(v9a, __shfl_xor_sync(0xffffffffu, v9a, off));
            v9b = fmaxf(v9b, __shfl_xor_sync(0xffffffffu, v9b, off));
        }
    }

    float cv[2];
    #pragma unroll
    for (int r = 0; r < 2; r++) {
        int ci = lane + r * 32;
        cv[r] = __fadd_rn(tv1[ci >> 3], tv2[ci & 7]);
    }
    float fs[5]; int fci[4];
    #pragma unroll
    for (int it = 0; it < 4; it++) {
        float bm; int bi;
        if (cv[0] >= cv[1]) { bm = cv[0]; bi = lane; }
        else                { bm = cv[1]; bi = lane + 32; }
        #pragma unroll
        for (int off = 16; off > 0; off >>= 1) {
            float om = __shfl_xor_sync(0xffffffffu, bm, off);
            int   oi = __shfl_xor_sync(0xffffffffu, bi, off);
            if (om > bm || (om == bm && oi < bi)) { bm = om; bi = oi; }
        }
        fs[it] = bm; fci[it] = bi;
        if ((bi & 31) == lane) cv[bi >> 5] = NEG_BIG;
    }
    if (flag) {
        float m5 = fmaxf(cv[0], cv[1]);
        #pragma unroll
        for (int off = 16; off > 0; off >>= 1)
            m5 = fmaxf(m5, __shfl_xor_sync(0xffffffffu, m5, off));
        fs[4] = m5;
    }

    if (lane == 0) {
        float m = fs[0];
        float e[4], sum = 0.0f;
        #pragma unroll
        for (int k = 0; k < 4; k++) { e[k] = expf(fs[k] - m); sum += e[k]; }
        float* out_scores  = out;
        float* out_experts = out + (size_t)N_TOK * H_HEADS * TOPK;
        #pragma unroll
        for (int k = 0; k < 4; k++) {
            int ci = fci[k];
            int i1 = ti1[ci >> 3];
            int i2 = ti2[ci & 7];
            out_scores [(size_t)gw * TOPK + k] = e[k] / sum;
            out_experts[(size_t)gw * TOPK + k] = (float)(i1 * S_KEYS + i2);
        }
        if (flag) {
            float mg = 1e30f;
            #pragma unroll
            for (int i = 0; i < 7; i++) {
                mg = fminf(mg, tv1[i] - tv1[i + 1]);
                mg = fminf(mg, tv2[i] - tv2[i + 1]);
            }
            mg = fminf(mg, tv1[7] - v9a);
            mg = fminf(mg, tv2[7] - v9b);
            #pragma unroll
            for (int i = 0; i < 4; i++) mg = fminf(mg, fs[i] - fs[i + 1]);
            if (mg < DELTA) {
                int idx = atomicAdd(&g_cnt, 1);
                if (idx < N_TOK * H_HEADS) g_list[idx] = gw;
            }
        }
    }
}

__global__ __launch_bounds__(256) void k_zero() { if (threadIdx.x == 0) g_cnt = 0; }

__global__ __launch_bounds__(256) void k_topk_p1(float* __restrict__ out)
{
    int gw   = (blockIdx.x * blockDim.x + threadIdx.x) >> 5;
    int lane = threadIdx.x & 31;
    if (gw >= N_TOK * H_HEADS) return;
    topk_row(gw, lane, out, true);
}

// =====================================================================
// Refine: recompute flagged rows with bitwise-frozen R7 arithmetic.
// =====================================================================
__global__ __launch_bounds__(256) void k_refine(
    const float* __restrict__ x, const float* __restrict__ Wq, const float* __restrict__ bq,
    const float* __restrict__ gamma, const float* __restrict__ beta)
{
    if ((int)blockIdx.x >= g_cnt) return;
    int gw = g_list[blockIdx.x];
    int n = gw >> 2, h = gw & 3;
    int tid = threadIdx.x;

    __shared__ float xs[D_MODEL];
    __shared__ float qh[Q_DIM];
    for (int i = tid; i < D_MODEL; i += 256) xs[i] = x[(size_t)n * D_MODEL + i];
    __syncthreads();

    #pragma unroll
    for (int o = 0; o < 2; o++) {
        int c = tid + o * 256;
        const float* wp = Wq + (size_t)h * D_MODEL * Q_DIM + c;
        float acc = 0.0f;
        #pragma unroll 8
        for (int k = 0; k < D_MODEL; k++)
            acc = fmaf(xs[k], wp[(size_t)k * Q_DIM], acc);
        float qv = acc + bq[h * Q_DIM + c];
        int col = h * Q_DIM + c;
        qh[c] = __fmul_rn(__fsub_rn(qv, g_mun[col]), g_rn[col]) * gamma[col] + beta[col];
    }
    __syncthreads();

    #pragma unroll
    for (int tbl = 0; tbl < 2; tbl++) {
        int j = tid;
        const float* kt = g_Kt + tbl * (HALF * S_KEYS) + j;
        const float* qq = qh + tbl * HALF;
        float acc = 0.0f;
        #pragma unroll 8
        for (int c = 0; c < HALF; c++)
            acc = fmaf(qq[c], kt[c * S_KEYS], acc);
        g_s[(size_t)n * HQ + h * Q_DIM + tbl * HALF + j] = acc;
    }
}

__global__ __launch_bounds__(256) void k_topk_p2(float* __restrict__ out)
{
    int wi   = (blockIdx.x * blockDim.x + threadIdx.x) >> 5;
    int lane = threadIdx.x & 31;
    if (wi >= g_cnt) return;
    topk_row(g_list[wi], lane, out, false);
}

// -------------------- launch --------------------
extern "C" void kernel_launch(void* const* d_in, const int* in_sizes, int n_in,
                              void* d_out, int out_size)
{
    const float* x     = (const float*)d_in[0];
    const float* Wq    = (const float*)d_in[1];
    const float* bq    = (const float*)d_in[2];
    const float* gamma = (const float*)d_in[3];
    const float* beta  = (const float*)d_in[4];
    const float* K1    = (const float*)d_in[5];
    const float* K2    = (const float*)d_in[6];
    float* out = (float*)d_out;

    cudaFuncSetAttribute(k_gemm_q_mma, cudaFuncAttributeMaxDynamicSharedMemorySize, SMEM_MMA);

    k_split_x<<<(N_TOK * D_MODEL) / (256 * 4), 256>>>(x);
    k_split_w<<<dim3(D_MODEL / 32, Q_DIM / 32, H_HEADS), dim3(32, 8)>>>(Wq);
    k_gemm_q_mma<<<dim3(N_TOK / 128, HQ / 64), 256, SMEM_MMA>>>(bq);
    k_mean_part<<<dim3(256, NPART), 256>>>();
    k_mean_fin<<<8, 256>>>();
    k_var_part<<<dim3(256, NPART), 256>>>();
    k_var_fin<<<8, 256>>>();
    k_transpose<<<512, 256>>>(K1, K2);
    k_gemm_s<<<dim3(128, 2, 8), 512>>>(gamma, beta);
    k_zero<<<1, 256>>>();
    k_topk_p1<<<(N_TOK * H_HEADS * 32) / 256, 256>>>(out);
    k_refine<<<N_TOK * H_HEADS, 256>>>(x, Wq, bq, gamma, beta);
    k_topk_p2<<<(N_TOK * H_HEADS) / 8, 256>>>(out);
}

// round 15
// speedup vs baseline: 1.2021x; 1.2021x over previous
#include <cuda_runtime.h>
#include <cuda_bf16.h>
#include <math.h>

#define N_TOK   16384
#define D_MODEL 2048
#define Q_DIM   512
#define H_HEADS 4
#define HQ      2048      // H * Q
#define HALF    256       // Q/2
#define S_KEYS  256
#define TOPK    4
#define BN_EPS  1e-5f
#define NEG_BIG (-1e30f)
#define NPART   4
#define CHUNK   (N_TOK / NPART)
#define DELTA   1e-4f     // suspicion margin (>> mma-path noise)

typedef unsigned long long u64;
typedef unsigned int u32;

// -------------------- device scratch (static, no allocation) --------------------
static __device__ float  g_q [(size_t)N_TOK * HQ];
static __device__ float  g_s [(size_t)N_TOK * HQ];
static __device__ float  g_pm[NPART][HQ];
static __device__ float  g_pv[NPART][HQ];
static __device__ float  g_mun[HQ];
static __device__ float  g_rn [HQ];
static __device__ float  g_Kt [2 * HALF * S_KEYS];
static __device__ int    g_cnt;
static __device__ int    g_list[N_TOK * H_HEADS];
// bf16 3-way splits of x (A) and transposed Wq (B, [h*512+n][k])
static __device__ __align__(16) __nv_bfloat16 g_xs1[(size_t)N_TOK * D_MODEL];
static __device__ __align__(16) __nv_bfloat16 g_xs2[(size_t)N_TOK * D_MODEL];
static __device__ __align__(16) __nv_bfloat16 g_xs3[(size_t)N_TOK * D_MODEL];
static __device__ __align__(16) __nv_bfloat16 g_ws1[(size_t)HQ * D_MODEL];
static __device__ __align__(16) __nv_bfloat16 g_ws2[(size_t)HQ * D_MODEL];
static __device__ __align__(16) __nv_bfloat16 g_ws3[(size_t)HQ * D_MODEL];

// -------------------- helpers --------------------
__device__ __forceinline__ u32 smem_u32(const void* p) {
    u32 a;
    asm("{ .reg .u64 t; cvta.to.shared.u64 t, %1; cvt.u32.u64 %0, t; }" : "=r"(a) : "l"(p));
    return a;
}
__device__ __forceinline__ u64 f2_pack(float lo, float hi) {
    u64 r; asm("mov.b64 %0, {%1, %2};" : "=l"(r) : "f"(lo), "f"(hi)); return r;
}
__device__ __forceinline__ void f2_unpack(u64 v, float& lo, float& hi) {
    asm("mov.b64 {%0, %1}, %2;" : "=f"(lo), "=f"(hi) : "l"(v));
}
__device__ __forceinline__ u64 f2_fma(u64 a, u64 b, u64 c) {
    u64 d; asm("fma.rn.f32x2 %0, %1, %2, %3;" : "=l"(d) : "l"(a), "l"(b), "l"(c)); return d;
}
__device__ __forceinline__ void mma_bf16(float* d, const u32* a, const u32* b) {
    asm volatile(
        "mma.sync.aligned.m16n8k16.row.col.f32.bf16.bf16.f32 "
        "{%0,%1,%2,%3}, {%4,%5,%6,%7}, {%8,%9}, {%0,%1,%2,%3};"
        : "+f"(d[0]), "+f"(d[1]), "+f"(d[2]), "+f"(d[3])
        : "r"(a[0]), "r"(a[1]), "r"(a[2]), "r"(a[3]), "r"(b[0]), "r"(b[1]));
}
#define CP_ASYNC16(dst, src) \
    asm volatile("cp.async.cg.shared.global [%0], [%1], 16;" :: "r"(dst), "l"(src))
#define CP_ASYNC_FENCE() do { \
    asm volatile("cp.async.commit_group;"); \
    asm volatile("cp.async.wait_group 0;"); \
} while (0)

// =====================================================================
// Split kernels
// =====================================================================
__device__ __forceinline__ void split3(float v, __nv_bfloat16& b1, __nv_bfloat16& b2, __nv_bfloat16& b3) {
    b1 = __float2bfloat16_rn(v);
    float r1 = v - __bfloat162float(b1);
    b2 = __float2bfloat16_rn(r1);
    float r2 = r1 - __bfloat162float(b2);
    b3 = __float2bfloat16_rn(r2);
}

__global__ __launch_bounds__(256) void k_split_x(const float* __restrict__ x)
{
    if (blockIdx.x == 0 && threadIdx.x == 0) g_cnt = 0;   // fold zeroing here
    size_t i0 = ((size_t)blockIdx.x * 256 + threadIdx.x) * 4;
    float4 v = *(const float4*)(x + i0);
    float vv[4] = {v.x, v.y, v.z, v.w};
    #pragma unroll
    for (int u = 0; u < 4; u++) {
        __nv_bfloat16 b1, b2, b3;
        split3(vv[u], b1, b2, b3);
        g_xs1[i0 + u] = b1; g_xs2[i0 + u] = b2; g_xs3[i0 + u] = b3;
    }
}

__global__ void k_split_w(const float* __restrict__ Wq)
{
    __shared__ float tile[32][33];
    int k0 = blockIdx.x * 32, n0 = blockIdx.y * 32, h = blockIdx.z;
    int tx = threadIdx.x, ty = threadIdx.y;
    #pragma unroll
    for (int q = 0; q < 4; q++) {
        int r = ty + q * 8;
        tile[r][tx] = Wq[(size_t)h * D_MODEL * Q_DIM + (size_t)(k0 + r) * Q_DIM + n0 + tx];
    }
    __syncthreads();
    #pragma unroll
    for (int q = 0; q < 4; q++) {
        int nn = ty + q * 8;
        float v = tile[tx][nn];
        __nv_bfloat16 b1, b2, b3;
        split3(v, b1, b2, b3);
        size_t o = (size_t)(h * Q_DIM + n0 + nn) * D_MODEL + k0 + tx;
        g_ws1[o] = b1; g_ws2[o] = b2; g_ws3[o] = b3;
    }
}

// =====================================================================
// Kernel 1: q = x @ Wq + bq via mma.sync m16n8k16 bf16, 3-split/6-product.
// BITWISE-IDENTICAL math to R14 (same k order, same hi/lo accumulator
// grouping, same mma sequence, same epilogue). Perf changes only:
// occupancy 2, cp.async tile loads, hoisted B-fragment LDS.
// Block 128x64, BK=32, 256 thr = 8 warps (4m x 2n), warp tile 32x32.
// =====================================================================
#define RSB     80
#define ASM_OFF(s) ((s) * 10240)                  // A: 128 rows * 80B
#define BSM_OFF(s) (30720 + (s) * 5120)           // B: 64 rows * 80B
#define SMEM_MMA 46080

__global__ __launch_bounds__(256, 2) void k_gemm_q_mma(const float* __restrict__ bq)
{
    extern __shared__ char smem[];
    const u32 sbase = smem_u32(smem);
    const int tid  = threadIdx.x;
    const int wid  = tid >> 5, lane = tid & 31;
    const int m0   = (wid & 3) * 32;
    const int n0   = (wid >> 2) * 32;
    const int row0 = blockIdx.x * 128;
    const int col0 = blockIdx.y * 64;

    float dh[2][4][4], dl[2][4][4];
    #pragma unroll
    for (int mf = 0; mf < 2; mf++)
        #pragma unroll
        for (int nf = 0; nf < 4; nf++)
            #pragma unroll
            for (int e = 0; e < 4; e++) { dh[mf][nf][e] = 0.0f; dl[mf][nf][e] = 0.0f; }

    const int lr = lane >> 2;
    const int lk = (lane & 3) * 2;

    // cp.async destination offsets (fixed per thread)
    const int ar0 = tid >> 2, ak0 = (tid & 3) * 8;           // A tranche 1 (+ tranche 2 at +256)
    const int ar1 = (tid + 256) >> 2, ak1 = ((tid + 256) & 3) * 8;

    for (int kt = 0; kt < D_MODEL; kt += 32) {
        #pragma unroll
        for (int s = 0; s < 3; s++) {
            const __nv_bfloat16* X = (s == 0) ? g_xs1 : (s == 1) ? g_xs2 : g_xs3;
            const __nv_bfloat16* W = (s == 0) ? g_ws1 : (s == 1) ? g_ws2 : g_ws3;
            CP_ASYNC16(sbase + ASM_OFF(s) + ar0 * RSB + ak0 * 2,
                       X + (size_t)(row0 + ar0) * D_MODEL + kt + ak0);
            CP_ASYNC16(sbase + ASM_OFF(s) + ar1 * RSB + ak1 * 2,
                       X + (size_t)(row0 + ar1) * D_MODEL + kt + ak1);
            CP_ASYNC16(sbase + BSM_OFF(s) + ar0 * RSB + ak0 * 2,
                       W + (size_t)(col0 + ar0) * D_MODEL + kt + ak0);
        }
        CP_ASYNC_FENCE();
        __syncthreads();

        #pragma unroll
        for (int ks = 0; ks < 2; ks++) {
            const int kb = ks * 16 + lk;
            // hoist ALL B fragments for this ks (reused across si)
            u32 bfr[3][4][2];
            #pragma unroll
            for (int sj = 0; sj < 3; sj++)
                #pragma unroll
                for (int nf = 0; nf < 4; nf++) {
                    const char* bb = smem + BSM_OFF(sj) + (size_t)(n0 + nf * 8 + lr) * RSB;
                    bfr[sj][nf][0] = *(const u32*)(bb + kb * 2);
                    bfr[sj][nf][1] = *(const u32*)(bb + kb * 2 + 16);
                }
            #pragma unroll
            for (int si = 0; si < 3; si++) {
                u32 a[2][4];
                #pragma unroll
                for (int mf = 0; mf < 2; mf++) {
                    const char* base = smem + ASM_OFF(si) + (size_t)(m0 + mf * 16 + lr) * RSB;
                    a[mf][0] = *(const u32*)(base + kb * 2);
                    a[mf][1] = *(const u32*)(base + 8 * RSB + kb * 2);
                    a[mf][2] = *(const u32*)(base + kb * 2 + 16);
                    a[mf][3] = *(const u32*)(base + 8 * RSB + kb * 2 + 16);
                }
                const int njmax = 3 - si;
                #pragma unroll
                for (int sj = 0; sj < 3; sj++) {
                    if (sj >= njmax) break;
                    #pragma unroll
                    for (int nf = 0; nf < 4; nf++) {
                        if (si == 0 && sj == 0) {
                            mma_bf16(dh[0][nf], a[0], bfr[sj][nf]);
                            mma_bf16(dh[1][nf], a[1], bfr[sj][nf]);
                        } else {
                            mma_bf16(dl[0][nf], a[0], bfr[sj][nf]);
                            mma_bf16(dl[1][nf], a[1], bfr[sj][nf]);
                        }
                    }
                }
            }
        }
        __syncthreads();
    }

    #pragma unroll
    for (int mf = 0; mf < 2; mf++) {
        #pragma unroll
        for (int nf = 0; nf < 4; nf++) {
            int r = row0 + m0 + mf * 16 + lr;
            int c = col0 + n0 + nf * 8 + lk;
            g_q[(size_t)r * HQ + c]           = (dh[mf][nf][0] + dl[mf][nf][0]) + bq[c];
            g_q[(size_t)r * HQ + c + 1]       = (dh[mf][nf][1] + dl[mf][nf][1]) + bq[c + 1];
            g_q[(size_t)(r + 8) * HQ + c]     = (dh[mf][nf][2] + dl[mf][nf][2]) + bq[c];
            g_q[(size_t)(r + 8) * HQ + c + 1] = (dh[mf][nf][3] + dl[mf][nf][3]) + bq[c + 1];
        }
    }
}

// =====================================================================
// Stats (frozen recipe, MLP-8 loads).
// =====================================================================
__global__ __launch_bounds__(256) void k_mean_part()
{
    int c    = blockIdx.x * 8 + (threadIdx.x >> 5);
    int b    = blockIdx.y;
    int lane = threadIdx.x & 31;
    float s = 0.0f;
    const float* p = g_q + ((size_t)b * CHUNK + lane) * HQ + c;
    #pragma unroll 1
    for (int j = 0; j < CHUNK / 32; j += 8) {
        float v[8];
        #pragma unroll
        for (int u = 0; u < 8; u++) v[u] = p[(size_t)(j + u) * 32 * HQ];
        #pragma unroll
        for (int u = 0; u < 8; u++) s = __fadd_rn(s, v[u]);
    }
    #pragma unroll
    for (int off = 16; off > 0; off >>= 1)
        s = __fadd_rn(s, __shfl_down_sync(0xffffffffu, s, off));
    if (lane == 0) g_pm[b][c] = s;
}

__global__ __launch_bounds__(256) void k_mean_fin()
{
    int c = blockIdx.x * 256 + threadIdx.x;
    float s = g_pm[0][c];
    #pragma unroll
    for (int b = 1; b < NPART; b++) s = __fadd_rn(s, g_pm[b][c]);
    g_mun[c] = s * (1.0f / (float)N_TOK);
}

__global__ __launch_bounds__(256) void k_var_part()
{
    int c    = blockIdx.x * 8 + (threadIdx.x >> 5);
    int b    = blockIdx.y;
    int lane = threadIdx.x & 31;
    float mu = g_mun[c];
    float s = 0.0f;
    const float* p = g_q + ((size_t)b * CHUNK + lane) * HQ + c;
    #pragma unroll 1
    for (int j = 0; j < CHUNK / 32; j += 8) {
        float v[8];
        #pragma unroll
        for (int u = 0; u < 8; u++) v[u] = p[(size_t)(j + u) * 32 * HQ];
        #pragma unroll
        for (int u = 0; u < 8; u++) {
            float dd = __fsub_rn(v[u], mu);
            s = __fadd_rn(s, __fmul_rn(dd, dd));
        }
    }
    #pragma unroll
    for (int off = 16; off > 0; off >>= 1)
        s = __fadd_rn(s, __shfl_down_sync(0xffffffffu, s, off));
    if (lane == 0) g_pv[b][c] = s;
}

__global__ __launch_bounds__(256) void k_var_fin()
{
    int c = blockIdx.x * 256 + threadIdx.x;
    float s = g_pv[0][c];
    #pragma unroll
    for (int b = 1; b < NPART; b++) s = __fadd_rn(s, g_pv[b][c]);
    float var = s * (1.0f / (float)N_TOK);
    g_rn[c] = rsqrtf(__fadd_rn(var, BN_EPS));
}

__global__ __launch_bounds__(256) void k_transpose(
    const float* __restrict__ K1, const float* __restrict__ K2)
{
    int idx = blockIdx.x * 256 + threadIdx.x;
    int tbl = idx >> 16;
    int c   = (idx >> 8) & 255;
    int k   = idx & 255;
    const float* Ksrc = tbl ? K2 : K1;
    g_Kt[idx] = Ksrc[k * HALF + c];
}

// =====================================================================
// Kernel 4: scoring GEMM (frozen recipe) on mma-q.
// =====================================================================
__global__ __launch_bounds__(512) void k_gemm_s(
    const float* __restrict__ gamma, const float* __restrict__ beta)
{
    __shared__ float As[16][128];
    __shared__ float Bs[16][128];

    const int tid = threadIdx.x;
    const int tx  = tid & 15;
    const int ty  = tid >> 4;

    const int z   = blockIdx.z;
    const int tbl = z >> 2;
    const int h   = z & 3;
    const int cb  = h * Q_DIM + tbl * HALF;

    const float* A  = g_q + (size_t)blockIdx.x * 128 * HQ + cb;
    const float* B  = g_Kt + (size_t)tbl * HALF * S_KEYS + blockIdx.y * 128;
    const float* mu = g_mun + cb;
    const float* rn = g_rn  + cb;
    const float* gm = gamma + cb;
    const float* bt = beta  + cb;

    u64 acc2[4][4];
    #pragma unroll
    for (int i = 0; i < 4; i++)
        #pragma unroll
        for (int m = 0; m < 4; m++) acc2[i][m] = 0ull;

    const int ar = tid >> 2;
    const int ac = (tid & 3) * 4;
    const int br = tid >> 5;
    const int bc = (tid & 31) * 4;

    for (int kt = 0; kt < HALF; kt += 16) {
        float4 va = *(const float4*)(A + (size_t)ar * HQ + kt + ac);
        int c0 = kt + ac;
        va.x = __fmul_rn(__fsub_rn(va.x, mu[c0 + 0]), rn[c0 + 0]) * gm[c0 + 0] + bt[c0 + 0];
        va.y = __fmul_rn(__fsub_rn(va.y, mu[c0 + 1]), rn[c0 + 1]) * gm[c0 + 1] + bt[c0 + 1];
        va.z = __fmul_rn(__fsub_rn(va.z, mu[c0 + 2]), rn[c0 + 2]) * gm[c0 + 2] + bt[c0 + 2];
        va.w = __fmul_rn(__fsub_rn(va.w, mu[c0 + 3]), rn[c0 + 3]) * gm[c0 + 3] + bt[c0 + 3];
        As[ac + 0][ar] = va.x; As[ac + 1][ar] = va.y;
        As[ac + 2][ar] = va.z; As[ac + 3][ar] = va.w;
        *(float4*)(&Bs[br][bc]) = *(const float4*)(B + (size_t)(kt + br) * S_KEYS + bc);
        __syncthreads();

        #pragma unroll
        for (int k = 0; k < 16; k++) {
            u64 a2[4], b2[4];
            #pragma unroll
            for (int i = 0; i < 4; i++) {
                float av = As[k][ty * 4 + i];
                a2[i] = f2_pack(av, av);
            }
            #pragma unroll
            for (int m = 0; m < 4; m++)
                b2[m] = *(const u64*)(&Bs[k][tx * 8 + m * 2]);
            #pragma unroll
            for (int i = 0; i < 4; i++)
                #pragma unroll
                for (int m = 0; m < 4; m++)
                    acc2[i][m] = f2_fma(a2[i], b2[m], acc2[i][m]);
        }
        __syncthreads();
    }

    float* C = g_s + (size_t)blockIdx.x * 128 * HQ + cb + blockIdx.y * 128;
    #pragma unroll
    for (int i = 0; i < 4; i++) {
        int r = ty * 4 + i;
        #pragma unroll
        for (int m = 0; m < 4; m++) {
            float lo, hi;
            f2_unpack(acc2[i][m], lo, hi);
            int c = tx * 8 + m * 2;
            C[(size_t)r * HQ + c + 0] = lo;
            C[(size_t)r * HQ + c + 1] = hi;
        }
    }
}

// =====================================================================
// Shared top-k device function (frozen algorithm).
// flag=true: also compute min decision margin and append to list.
// =====================================================================
__device__ __forceinline__ void topk_row(int gw, int lane, float* out, bool flag)
{
    int n = gw >> 2;
    int h = gw & 3;

    const float* s1 = g_s + (size_t)n * HQ + h * Q_DIM;
    const float* s2 = s1 + HALF;

    float v1[8], v2[8];
    #pragma unroll
    for (int t = 0; t < 8; t++) { v1[t] = s1[t * 32 + lane]; v2[t] = s2[t * 32 + lane]; }

    float tv1[8], tv2[8];
    int   ti1[8], ti2[8];

    #pragma unroll
    for (int it = 0; it < 8; it++) {
        float bm = NEG_BIG; int bi = 0x7fffffff;
        #pragma unroll
        for (int t = 0; t < 8; t++)
            if (v1[t] > bm) { bm = v1[t]; bi = t * 32 + lane; }
        #pragma unroll
        for (int off = 16; off > 0; off >>= 1) {
            float om = __shfl_xor_sync(0xffffffffu, bm, off);
            int   oi = __shfl_xor_sync(0xffffffffu, bi, off);
            if (om > bm || (om == bm && oi < bi)) { bm = om; bi = oi; }
        }
        tv1[it] = bm; ti1[it] = bi;
        if ((bi & 31) == lane) v1[bi >> 5] = NEG_BIG;
    }
    #pragma unroll
    for (int it = 0; it < 8; it++) {
        float bm = NEG_BIG; int bi = 0x7fffffff;
        #pragma unroll
        for (int t = 0; t < 8; t++)
            if (v2[t] > bm) { bm = v2[t]; bi = t * 32 + lane; }
        #pragma unroll
        for (int off = 16; off > 0; off >>= 1) {
            float om = __shfl_xor_sync(0xffffffffu, bm, off);
            int   oi = __shfl_xor_sync(0xffffffffu, bi, off);
            if (om > bm || (om == bm && oi < bi)) { bm = om; bi = oi; }
        }
        tv2[it] = bm; ti2[it] = bi;
        if ((bi & 31) == lane) v2[bi >> 5] = NEG_BIG;
    }

    float v9a = NEG_BIG, v9b = NEG_BIG;
    if (flag) {
        #pragma unroll
        for (int t = 0; t < 8; t++) { v9a = fmaxf(v9a, v1[t]); v9b = fmaxf(v9b, v2[t]); }
        #pragma unroll
        for (int off = 16; off > 0; off >>= 1) {
            v9a = fmaxf(v9a, __shfl_xor_sync(0xffffffffu, v9a, off));
            v9b = fmaxf(v9b, __shfl_xor_sync(0xffffffffu, v9b, off));
        }
    }

    float cv[2];
    #pragma unroll
    for (int r = 0; r < 2; r++) {
        int ci = lane + r * 32;
        cv[r] = __fadd_rn(tv1[ci >> 3], tv2[ci & 7]);
    }
    float fs[5]; int fci[4];
    #pragma unroll
    for (int it = 0; it < 4; it++) {
        float bm; int bi;
        if (cv[0] >= cv[1]) { bm = cv[0]; bi = lane; }
        else                { bm = cv[1]; bi = lane + 32; }
        #pragma unroll
        for (int off = 16; off > 0; off >>= 1) {
            float om = __shfl_xor_sync(0xffffffffu, bm, off);
            int   oi = __shfl_xor_sync(0xffffffffu, bi, off);
            if (om > bm || (om == bm && oi < bi)) { bm = om; bi = oi; }
        }
        fs[it] = bm; fci[it] = bi;
        if ((bi & 31) == lane) cv[bi >> 5] = NEG_BIG;
    }
    if (flag) {
        float m5 = fmaxf(cv[0], cv[1]);
        #pragma unroll
        for (int off = 16; off > 0; off >>= 1)
            m5 = fmaxf(m5, __shfl_xor_sync(0xffffffffu, m5, off));
        fs[4] = m5;
    }

    if (lane == 0) {
        float m = fs[0];
        float e[4], sum = 0.0f;
        #pragma unroll
        for (int k = 0; k < 4; k++) { e[k] = expf(fs[k] - m); sum += e[k]; }
        float* out_scores  = out;
        float* out_experts = out + (size_t)N_TOK * H_HEADS * TOPK;
        #pragma unroll
        for (int k = 0; k < 4; k++) {
            int ci = fci[k];
            int i1 = ti1[ci >> 3];
            int i2 = ti2[ci & 7];
            out_scores [(size_t)gw * TOPK + k] = e[k] / sum;
            out_experts[(size_t)gw * TOPK + k] = (float)(i1 * S_KEYS + i2);
        }
        if (flag) {
            float mg = 1e30f;
            #pragma unroll
            for (int i = 0; i < 7; i++) {
                mg = fminf(mg, tv1[i] - tv1[i + 1]);
                mg = fminf(mg, tv2[i] - tv2[i + 1]);
            }
            mg = fminf(mg, tv1[7] - v9a);
            mg = fminf(mg, tv2[7] - v9b);
            #pragma unroll
            for (int i = 0; i < 4; i++) mg = fminf(mg, fs[i] - fs[i + 1]);
            if (mg < DELTA) {
                int idx = atomicAdd(&g_cnt, 1);
                if (idx < N_TOK * H_HEADS) g_list[idx] = gw;
            }
        }
    }
}

__global__ __launch_bounds__(256) void k_topk_p1(float* __restrict__ out)
{
    int gw   = (blockIdx.x * blockDim.x + threadIdx.x) >> 5;
    int lane = threadIdx.x & 31;
    if (gw >= N_TOK * H_HEADS) return;
    topk_row(gw, lane, out, true);
}

// =====================================================================
// Refine: recompute flagged rows with bitwise-frozen R7 arithmetic.
// =====================================================================
__global__ __launch_bounds__(256) void k_refine(
    const float* __restrict__ x, const float* __restrict__ Wq, const float* __restrict__ bq,
    const float* __restrict__ gamma, const float* __restrict__ beta)
{
    if ((int)blockIdx.x >= g_cnt) return;
    int gw = g_list[blockIdx.x];
    int n = gw >> 2, h = gw & 3;
    int tid = threadIdx.x;

    __shared__ float xs[D_MODEL];
    __shared__ float qh[Q_DIM];
    for (int i = tid; i < D_MODEL; i += 256) xs[i] = x[(size_t)n * D_MODEL + i];
    __syncthreads();

    #pragma unroll
    for (int o = 0; o < 2; o++) {
        int c = tid + o * 256;
        const float* wp = Wq + (size_t)h * D_MODEL * Q_DIM + c;
        float acc = 0.0f;
        #pragma unroll 8
        for (int k = 0; k < D_MODEL; k++)
            acc = fmaf(xs[k], wp[(size_t)k * Q_DIM], acc);
        float qv = acc + bq[h * Q_DIM + c];
        int col = h * Q_DIM + c;
        qh[c] = __fmul_rn(__fsub_rn(qv, g_mun[col]), g_rn[col]) * gamma[col] + beta[col];
    }
    __syncthreads();

    #pragma unroll
    for (int tbl = 0; tbl < 2; tbl++) {
        int j = tid;
        const float* kt = g_Kt + tbl * (HALF * S_KEYS) + j;
        const float* qq = qh + tbl * HALF;
        float acc = 0.0f;
        #pragma unroll 8
        for (int c = 0; c < HALF; c++)
            acc = fmaf(qq[c], kt[c * S_KEYS], acc);
        g_s[(size_t)n * HQ + h * Q_DIM + tbl * HALF + j] = acc;
    }
}

__global__ __launch_bounds__(256) void k_topk_p2(float* __restrict__ out)
{
    int wi   = (blockIdx.x * blockDim.x + threadIdx.x) >> 5;
    int lane = threadIdx.x & 31;
    if (wi >= g_cnt) return;
    topk_row(g_list[wi], lane, out, false);
}

// -------------------- launch --------------------
extern "C" void kernel_launch(void* const* d_in, const int* in_sizes, int n_in,
                              void* d_out, int out_size)
{
    const float* x     = (const float*)d_in[0];
    const float* Wq    = (const float*)d_in[1];
    const float* bq    = (const float*)d_in[2];
    const float* gamma = (const float*)d_in[3];
    const float* beta  = (const float*)d_in[4];
    const float* K1    = (const float*)d_in[5];
    const float* K2    = (const float*)d_in[6];
    float* out = (float*)d_out;

    cudaFuncSetAttribute(k_gemm_q_mma, cudaFuncAttributeMaxDynamicSharedMemorySize, SMEM_MMA);

    k_split_x<<<(N_TOK * D_MODEL) / (256 * 4), 256>>>(x);
    k_split_w<<<dim3(D_MODEL / 32, Q_DIM / 32, H_HEADS), dim3(32, 8)>>>(Wq);
    k_gemm_q_mma<<<dim3(N_TOK / 128, HQ / 64), 256, SMEM_MMA>>>(bq);
    k_mean_part<<<dim3(256, NPART), 256>>>();
    k_mean_fin<<<8, 256>>>();
    k_var_part<<<dim3(256, NPART), 256>>>();
    k_var_fin<<<8, 256>>>();
    k_transpose<<<512, 256>>>(K1, K2);
    k_gemm_s<<<dim3(128, 2, 8), 512>>>(gamma, beta);
    k_topk_p1<<<(N_TOK * H_HEADS * 32) / 256, 256>>>(out);
    k_refine<<<N_TOK * H_HEADS, 256>>>(x, Wq, bq, gamma, beta);
    k_topk_p2<<<(N_TOK * H_HEADS) / 8, 256>>>(out);
}

// round 16
// speedup vs baseline: 1.2982x; 1.0799x over previous
#include <cuda_runtime.h>
#include <cuda_bf16.h>
#include <math.h>

#define N_TOK   16384
#define D_MODEL 2048
#define Q_DIM   512
#define H_HEADS 4
#define HQ      2048      // H * Q
#define HALF    256       // Q/2
#define S_KEYS  256
#define TOPK    4
#define BN_EPS  1e-5f
#define NEG_BIG (-1e30f)
#define NPART   4
#define CHUNK   (N_TOK / NPART)
#define DELTA   1e-4f     // suspicion margin (>> mma-path noise)

typedef unsigned long long u64;
typedef unsigned int u32;

// -------------------- device scratch (static, no allocation) --------------------
static __device__ float  g_q [(size_t)N_TOK * HQ];
static __device__ float  g_s [(size_t)N_TOK * HQ];
static __device__ float  g_pm[NPART][HQ];
static __device__ float  g_pv[NPART][HQ];
static __device__ float  g_mun[HQ];
static __device__ float  g_rn [HQ];
static __device__ float  g_Kt [2 * HALF * S_KEYS];
static __device__ int    g_cnt;
static __device__ int    g_list[N_TOK * H_HEADS];
// bf16 3-way splits of x (A) and transposed Wq (B, [h*512+n][k])
static __device__ __align__(16) __nv_bfloat16 g_xs1[(size_t)N_TOK * D_MODEL];
static __device__ __align__(16) __nv_bfloat16 g_xs2[(size_t)N_TOK * D_MODEL];
static __device__ __align__(16) __nv_bfloat16 g_xs3[(size_t)N_TOK * D_MODEL];
static __device__ __align__(16) __nv_bfloat16 g_ws1[(size_t)HQ * D_MODEL];
static __device__ __align__(16) __nv_bfloat16 g_ws2[(size_t)HQ * D_MODEL];
static __device__ __align__(16) __nv_bfloat16 g_ws3[(size_t)HQ * D_MODEL];

// -------------------- helpers --------------------
__device__ __forceinline__ u32 smem_u32(const void* p) {
    u32 a;
    asm("{ .reg .u64 t; cvta.to.shared.u64 t, %1; cvt.u32.u64 %0, t; }" : "=r"(a) : "l"(p));
    return a;
}
__device__ __forceinline__ u64 f2_pack(float lo, float hi) {
    u64 r; asm("mov.b64 %0, {%1, %2};" : "=l"(r) : "f"(lo), "f"(hi)); return r;
}
__device__ __forceinline__ void f2_unpack(u64 v, float& lo, float& hi) {
    asm("mov.b64 {%0, %1}, %2;" : "=f"(lo), "=f"(hi) : "l"(v));
}
__device__ __forceinline__ u64 f2_fma(u64 a, u64 b, u64 c) {
    u64 d; asm("fma.rn.f32x2 %0, %1, %2, %3;" : "=l"(d) : "l"(a), "l"(b), "l"(c)); return d;
}
__device__ __forceinline__ void mma_bf16(float* d, const u32* a, const u32* b) {
    asm volatile(
        "mma.sync.aligned.m16n8k16.row.col.f32.bf16.bf16.f32 "
        "{%0,%1,%2,%3}, {%4,%5,%6,%7}, {%8,%9}, {%0,%1,%2,%3};"
        : "+f"(d[0]), "+f"(d[1]), "+f"(d[2]), "+f"(d[3])
        : "r"(a[0]), "r"(a[1]), "r"(a[2]), "r"(a[3]), "r"(b[0]), "r"(b[1]));
}
__device__ __forceinline__ void ldsm_x4(u32& r0, u32& r1, u32& r2, u32& r3, u32 addr) {
    asm volatile("ldmatrix.sync.aligned.m8n8.x4.shared.b16 {%0,%1,%2,%3}, [%4];"
                 : "=r"(r0), "=r"(r1), "=r"(r2), "=r"(r3) : "r"(addr));
}
#define CP_ASYNC16(dst, src) \
    asm volatile("cp.async.cg.shared.global [%0], [%1], 16;" :: "r"(dst), "l"(src))

// =====================================================================
// Split kernels
// =====================================================================
__device__ __forceinline__ void split3(float v, __nv_bfloat16& b1, __nv_bfloat16& b2, __nv_bfloat16& b3) {
    b1 = __float2bfloat16_rn(v);
    float r1 = v - __bfloat162float(b1);
    b2 = __float2bfloat16_rn(r1);
    float r2 = r1 - __bfloat162float(b2);
    b3 = __float2bfloat16_rn(r2);
}

__global__ __launch_bounds__(256) void k_split_x(const float* __restrict__ x)
{
    if (blockIdx.x == 0 && threadIdx.x == 0) g_cnt = 0;
    size_t i0 = ((size_t)blockIdx.x * 256 + threadIdx.x) * 4;
    float4 v = *(const float4*)(x + i0);
    float vv[4] = {v.x, v.y, v.z, v.w};
    #pragma unroll
    for (int u = 0; u < 4; u++) {
        __nv_bfloat16 b1, b2, b3;
        split3(vv[u], b1, b2, b3);
        g_xs1[i0 + u] = b1; g_xs2[i0 + u] = b2; g_xs3[i0 + u] = b3;
    }
}

__global__ void k_split_w(const float* __restrict__ Wq)
{
    __shared__ float tile[32][33];
    int k0 = blockIdx.x * 32, n0 = blockIdx.y * 32, h = blockIdx.z;
    int tx = threadIdx.x, ty = threadIdx.y;
    #pragma unroll
    for (int q = 0; q < 4; q++) {
        int r = ty + q * 8;
        tile[r][tx] = Wq[(size_t)h * D_MODEL * Q_DIM + (size_t)(k0 + r) * Q_DIM + n0 + tx];
    }
    __syncthreads();
    #pragma unroll
    for (int q = 0; q < 4; q++) {
        int nn = ty + q * 8;
        float v = tile[tx][nn];
        __nv_bfloat16 b1, b2, b3;
        split3(v, b1, b2, b3);
        size_t o = (size_t)(h * Q_DIM + n0 + nn) * D_MODEL + k0 + tx;
        g_ws1[o] = b1; g_ws2[o] = b2; g_ws3[o] = b3;
    }
}

// =====================================================================
// Kernel 1: q = x @ Wq + bq via mma.sync m16n8k16 bf16, 3-split/6-product.
// BITWISE-IDENTICAL math to R14/R15 (same kt order, same hi/lo grouping,
// same mma issue sequence, same epilogue). Perf-only changes:
//  - grid axes swapped (colTile fast) -> A-splits L2-resident per wave
//  - ldmatrix.x4 fragment loads (4x fewer LDS issues, same register values)
//  - 2-stage cp.async double buffering (loads overlap mma)
// Block 128x64, BK=32, 256 thr = 8 warps (4m x 2n), warp tile 32x32.
// =====================================================================
#define RSB      80
#define ASM_OFF(s) ((s) * 10240)                  // A: 128 rows * 80B
#define BSM_OFF(s) (30720 + (s) * 5120)           // B: 64 rows * 80B
#define STAGE_B  46080
#define SMEM_MMA (2 * STAGE_B)                    // 92160

__global__ __launch_bounds__(256, 2) void k_gemm_q_mma(const float* __restrict__ bq)
{
    extern __shared__ char smem[];
    const u32 sbase = smem_u32(smem);
    const int tid  = threadIdx.x;
    const int wid  = tid >> 5, lane = tid & 31;
    const int m0   = (wid & 3) * 32;
    const int n0   = (wid >> 2) * 32;
    const int col0 = blockIdx.x * 64;       // colTile on FAST axis (L2 reuse of A)
    const int row0 = blockIdx.y * 128;

    float dh[2][4][4], dl[2][4][4];
    #pragma unroll
    for (int mf = 0; mf < 2; mf++)
        #pragma unroll
        for (int nf = 0; nf < 4; nf++)
            #pragma unroll
            for (int e = 0; e < 4; e++) { dh[mf][nf][e] = 0.0f; dl[mf][nf][e] = 0.0f; }

    // ldmatrix lane-addressing (tile t = lane>>3, row r = lane&7)
    const int lt = lane >> 3, lrr = lane & 7;
    // A tiles: t0 rows+0 @+0, t1 rows+8 @+0, t2 rows+0 @+16, t3 rows+8 @+16
    u32 aRow[2];
    #pragma unroll
    for (int mf = 0; mf < 2; mf++)
        aRow[mf] = sbase + (u32)((m0 + mf * 16 + (lt & 1) * 8 + lrr) * RSB + (lt >> 1) * 16);
    // B tiles: t0 rows np*16+0 @+0, t1 same rows @+16, t2 rows+8 @+0, t3 rows+8 @+16
    u32 bRow[2];
    #pragma unroll
    for (int np = 0; np < 2; np++)
        bRow[np] = sbase + (u32)(BSM_OFF(0) + (n0 + np * 16 + (lt >> 1) * 8 + lrr) * RSB + (lt & 1) * 16);

    // cp.async offsets
    const int ar0 = tid >> 2, ak0 = (tid & 3) * 8;
    const int ar1 = (tid + 256) >> 2, ak1 = ((tid + 256) & 3) * 8;

    // ---- prologue: load stage 0 ----
    #pragma unroll
    for (int s = 0; s < 3; s++) {
        const __nv_bfloat16* X = (s == 0) ? g_xs1 : (s == 1) ? g_xs2 : g_xs3;
        const __nv_bfloat16* W = (s == 0) ? g_ws1 : (s == 1) ? g_ws2 : g_ws3;
        CP_ASYNC16(sbase + ASM_OFF(s) + ar0 * RSB + ak0 * 2,
                   X + (size_t)(row0 + ar0) * D_MODEL + ak0);
        CP_ASYNC16(sbase + ASM_OFF(s) + ar1 * RSB + ak1 * 2,
                   X + (size_t)(row0 + ar1) * D_MODEL + ak1);
        CP_ASYNC16(sbase + BSM_OFF(s) + ar0 * RSB + ak0 * 2,
                   W + (size_t)(col0 + ar0) * D_MODEL + ak0);
    }
    asm volatile("cp.async.commit_group;");

    for (int kt = 0; kt < D_MODEL; kt += 32) {
        const u32 stoff = (u32)(((kt >> 5) & 1) * STAGE_B);
        const int ktn = kt + 32;
        if (ktn < D_MODEL) {
            const u32 nstoff = (u32)(((ktn >> 5) & 1) * STAGE_B);
            #pragma unroll
            for (int s = 0; s < 3; s++) {
                const __nv_bfloat16* X = (s == 0) ? g_xs1 : (s == 1) ? g_xs2 : g_xs3;
                const __nv_bfloat16* W = (s == 0) ? g_ws1 : (s == 1) ? g_ws2 : g_ws3;
                CP_ASYNC16(sbase + nstoff + ASM_OFF(s) + ar0 * RSB + ak0 * 2,
                           X + (size_t)(row0 + ar0) * D_MODEL + ktn + ak0);
                CP_ASYNC16(sbase + nstoff + ASM_OFF(s) + ar1 * RSB + ak1 * 2,
                           X + (size_t)(row0 + ar1) * D_MODEL + ktn + ak1);
                CP_ASYNC16(sbase + nstoff + BSM_OFF(s) + ar0 * RSB + ak0 * 2,
                           W + (size_t)(col0 + ar0) * D_MODEL + ktn + ak0);
            }
            asm volatile("cp.async.commit_group;");
            asm volatile("cp.async.wait_group 1;");
        } else {
            asm volatile("cp.async.wait_group 0;");
        }
        __syncthreads();

        #pragma unroll
        for (int ks = 0; ks < 2; ks++) {
            const u32 ko = stoff + ks * 32;
            // hoist ALL B fragments (same values as R15's bfr hoist)
            u32 bfr[3][4][2];
            #pragma unroll
            for (int sj = 0; sj < 3; sj++)
                #pragma unroll
                for (int np = 0; np < 2; np++)
                    ldsm_x4(bfr[sj][2 * np][0], bfr[sj][2 * np][1],
                            bfr[sj][2 * np + 1][0], bfr[sj][2 * np + 1][1],
                            bRow[np] + sj * 5120 + ko);
            // hoist A fragments
            u32 afr[3][2][4];
            #pragma unroll
            for (int si = 0; si < 3; si++)
                #pragma unroll
                for (int mf = 0; mf < 2; mf++)
                    ldsm_x4(afr[si][mf][0], afr[si][mf][1], afr[si][mf][2], afr[si][mf][3],
                            aRow[mf] + si * 10240 + ko);
            // mma issue order IDENTICAL to R14/R15: si -> sj -> nf -> (mf0, mf1)
            #pragma unroll
            for (int si = 0; si < 3; si++) {
                const int njmax = 3 - si;
                #pragma unroll
                for (int sj = 0; sj < 3; sj++) {
                    if (sj >= njmax) break;
                    #pragma unroll
                    for (int nf = 0; nf < 4; nf++) {
                        if (si == 0 && sj == 0) {
                            mma_bf16(dh[0][nf], afr[0][0], bfr[sj][nf]);
                            mma_bf16(dh[1][nf], afr[0][1], bfr[sj][nf]);
                        } else {
                            mma_bf16(dl[0][nf], afr[si][0], bfr[sj][nf]);
                            mma_bf16(dl[1][nf], afr[si][1], bfr[sj][nf]);
                        }
                    }
                }
            }
        }
        __syncthreads();
    }

    const int lr = lane >> 2;
    const int lk = (lane & 3) * 2;
    #pragma unroll
    for (int mf = 0; mf < 2; mf++) {
        #pragma unroll
        for (int nf = 0; nf < 4; nf++) {
            int r = row0 + m0 + mf * 16 + lr;
            int c = col0 + n0 + nf * 8 + lk;
            g_q[(size_t)r * HQ + c]           = (dh[mf][nf][0] + dl[mf][nf][0]) + bq[c];
            g_q[(size_t)r * HQ + c + 1]       = (dh[mf][nf][1] + dl[mf][nf][1]) + bq[c + 1];
            g_q[(size_t)(r + 8) * HQ + c]     = (dh[mf][nf][2] + dl[mf][nf][2]) + bq[c];
            g_q[(size_t)(r + 8) * HQ + c + 1] = (dh[mf][nf][3] + dl[mf][nf][3]) + bq[c + 1];
        }
    }
}

// =====================================================================
// Stats (frozen recipe, MLP-8 loads).
// =====================================================================
__global__ __launch_bounds__(256) void k_mean_part()
{
    int c    = blockIdx.x * 8 + (threadIdx.x >> 5);
    int b    = blockIdx.y;
    int lane = threadIdx.x & 31;
    float s = 0.0f;
    const float* p = g_q + ((size_t)b * CHUNK + lane) * HQ + c;
    #pragma unroll 1
    for (int j = 0; j < CHUNK / 32; j += 8) {
        float v[8];
        #pragma unroll
        for (int u = 0; u < 8; u++) v[u] = p[(size_t)(j + u) * 32 * HQ];
        #pragma unroll
        for (int u = 0; u < 8; u++) s = __fadd_rn(s, v[u]);
    }
    #pragma unroll
    for (int off = 16; off > 0; off >>= 1)
        s = __fadd_rn(s, __shfl_down_sync(0xffffffffu, s, off));
    if (lane == 0) g_pm[b][c] = s;
}

__global__ __launch_bounds__(256) void k_mean_fin()
{
    int c = blockIdx.x * 256 + threadIdx.x;
    float s = g_pm[0][c];
    #pragma unroll
    for (int b = 1; b < NPART; b++) s = __fadd_rn(s, g_pm[b][c]);
    g_mun[c] = s * (1.0f / (float)N_TOK);
}

__global__ __launch_bounds__(256) void k_var_part()
{
    int c    = blockIdx.x * 8 + (threadIdx.x >> 5);
    int b    = blockIdx.y;
    int lane = threadIdx.x & 31;
    float mu = g_mun[c];
    float s = 0.0f;
    const float* p = g_q + ((size_t)b * CHUNK + lane) * HQ + c;
    #pragma unroll 1
    for (int j = 0; j < CHUNK / 32; j += 8) {
        float v[8];
        #pragma unroll
        for (int u = 0; u < 8; u++) v[u] = p[(size_t)(j + u) * 32 * HQ];
        #pragma unroll
        for (int u = 0; u < 8; u++) {
            float dd = __fsub_rn(v[u], mu);
            s = __fadd_rn(s, __fmul_rn(dd, dd));
        }
    }
    #pragma unroll
    for (int off = 16; off > 0; off >>= 1)
        s = __fadd_rn(s, __shfl_down_sync(0xffffffffu, s, off));
    if (lane == 0) g_pv[b][c] = s;
}

__global__ __launch_bounds__(256) void k_var_fin()
{
    int c = blockIdx.x * 256 + threadIdx.x;
    float s = g_pv[0][c];
    #pragma unroll
    for (int b = 1; b < NPART; b++) s = __fadd_rn(s, g_pv[b][c]);
    float var = s * (1.0f / (float)N_TOK);
    g_rn[c] = rsqrtf(__fadd_rn(var, BN_EPS));
}

__global__ __launch_bounds__(256) void k_transpose(
    const float* __restrict__ K1, const float* __restrict__ K2)
{
    int idx = blockIdx.x * 256 + threadIdx.x;
    int tbl = idx >> 16;
    int c   = (idx >> 8) & 255;
    int k   = idx & 255;
    const float* Ksrc = tbl ? K2 : K1;
    g_Kt[idx] = Ksrc[k * HALF + c];
}

// =====================================================================
// Kernel 4: scoring GEMM (frozen recipe) on mma-q.
// =====================================================================
__global__ __launch_bounds__(512) void k_gemm_s(
    const float* __restrict__ gamma, const float* __restrict__ beta)
{
    __shared__ float As[16][128];
    __shared__ float Bs[16][128];

    const int tid = threadIdx.x;
    const int tx  = tid & 15;
    const int ty  = tid >> 4;

    const int z   = blockIdx.z;
    const int tbl = z >> 2;
    const int h   = z & 3;
    const int cb  = h * Q_DIM + tbl * HALF;

    const float* A  = g_q + (size_t)blockIdx.x * 128 * HQ + cb;
    const float* B  = g_Kt + (size_t)tbl * HALF * S_KEYS + blockIdx.y * 128;
    const float* mu = g_mun + cb;
    const float* rn = g_rn  + cb;
    const float* gm = gamma + cb;
    const float* bt = beta  + cb;

    u64 acc2[4][4];
    #pragma unroll
    for (int i = 0; i < 4; i++)
        #pragma unroll
        for (int m = 0; m < 4; m++) acc2[i][m] = 0ull;

    const int ar = tid >> 2;
    const int ac = (tid & 3) * 4;
    const int br = tid >> 5;
    const int bc = (tid & 31) * 4;

    for (int kt = 0; kt < HALF; kt += 16) {
        float4 va = *(const float4*)(A + (size_t)ar * HQ + kt + ac);
        int c0 = kt + ac;
        va.x = __fmul_rn(__fsub_rn(va.x, mu[c0 + 0]), rn[c0 + 0]) * gm[c0 + 0] + bt[c0 + 0];
        va.y = __fmul_rn(__fsub_rn(va.y, mu[c0 + 1]), rn[c0 + 1]) * gm[c0 + 1] + bt[c0 + 1];
        va.z = __fmul_rn(__fsub_rn(va.z, mu[c0 + 2]), rn[c0 + 2]) * gm[c0 + 2] + bt[c0 + 2];
        va.w = __fmul_rn(__fsub_rn(va.w, mu[c0 + 3]), rn[c0 + 3]) * gm[c0 + 3] + bt[c0 + 3];
        As[ac + 0][ar] = va.x; As[ac + 1][ar] = va.y;
        As[ac + 2][ar] = va.z; As[ac + 3][ar] = va.w;
        *(float4*)(&Bs[br][bc]) = *(const float4*)(B + (size_t)(kt + br) * S_KEYS + bc);
        __syncthreads();

        #pragma unroll
        for (int k = 0; k < 16; k++) {
            u64 a2[4], b2[4];
            #pragma unroll
            for (int i = 0; i < 4; i++) {
                float av = As[k][ty * 4 + i];
                a2[i] = f2_pack(av, av);
            }
            #pragma unroll
            for (int m = 0; m < 4; m++)
                b2[m] = *(const u64*)(&Bs[k][tx * 8 + m * 2]);
            #pragma unroll
            for (int i = 0; i < 4; i++)
                #pragma unroll
                for (int m = 0; m < 4; m++)
                    acc2[i][m] = f2_fma(a2[i], b2[m], acc2[i][m]);
        }
        __syncthreads();
    }

    float* C = g_s + (size_t)blockIdx.x * 128 * HQ + cb + blockIdx.y * 128;
    #pragma unroll
    for (int i = 0; i < 4; i++) {
        int r = ty * 4 + i;
        #pragma unroll
        for (int m = 0; m < 4; m++) {
            float lo, hi;
            f2_unpack(acc2[i][m], lo, hi);
            int c = tx * 8 + m * 2;
            C[(size_t)r * HQ + c + 0] = lo;
            C[(size_t)r * HQ + c + 1] = hi;
        }
    }
}

// =====================================================================
// Shared top-k device function (frozen algorithm).
// =====================================================================
__device__ __forceinline__ void topk_row(int gw, int lane, float* out, bool flag)
{
    int n = gw >> 2;
    int h = gw & 3;

    const float* s1 = g_s + (size_t)n * HQ + h * Q_DIM;
    const float* s2 = s1 + HALF;

    float v1[8], v2[8];
    #pragma unroll
    for (int t = 0; t < 8; t++) { v1[t] = s1[t * 32 + lane]; v2[t] = s2[t * 32 + lane]; }

    float tv1[8], tv2[8];
    int   ti1[8], ti2[8];

    #pragma unroll
    for (int it = 0; it < 8; it++) {
        float bm = NEG_BIG; int bi = 0x7fffffff;
        #pragma unroll
        for (int t = 0; t < 8; t++)
            if (v1[t] > bm) { bm = v1[t]; bi = t * 32 + lane; }
        #pragma unroll
        for (int off = 16; off > 0; off >>= 1) {
            float om = __shfl_xor_sync(0xffffffffu, bm, off);
            int   oi = __shfl_xor_sync(0xffffffffu, bi, off);
            if (om > bm || (om == bm && oi < bi)) { bm = om; bi = oi; }
        }
        tv1[it] = bm; ti1[it] = bi;
        if ((bi & 31) == lane) v1[bi >> 5] = NEG_BIG;
    }
    #pragma unroll
    for (int it = 0; it < 8; it++) {
        float bm = NEG_BIG; int bi = 0x7fffffff;
        #pragma unroll
        for (int t = 0; t < 8; t++)
            if (v2[t] > bm) { bm = v2[t]; bi = t * 32 + lane; }
        #pragma unroll
        for (int off = 16; off > 0; off >>= 1) {
            float om = __shfl_xor_sync(0xffffffffu, bm, off);
            int   oi = __shfl_xor_sync(0xffffffffu, bi, off);
            if (om > bm || (om == bm && oi < bi)) { bm = om; bi = oi; }
        }
        tv2[it] = bm; ti2[it] = bi;
        if ((bi & 31) == lane) v2[bi >> 5] = NEG_BIG;
    }

    float v9a = NEG_BIG, v9b = NEG_BIG;
    if (flag) {
        #pragma unroll
        for (int t = 0; t < 8; t++) { v9a = fmaxf(v9a, v1[t]); v9b = fmaxf(v9b, v2[t]); }
        #pragma unroll
        for (int off = 16; off > 0; off >>= 1) {
            v9a = fmaxf(v9a, __shfl_xor_sync(0xffffffffu, v9a, off));
            v9b = fmaxf(v9b, __shfl_xor_sync(0xffffffffu, v9b, off));
        }
    }

    float cv[2];
    #pragma unroll
    for (int r = 0; r < 2; r++) {
        int ci = lane + r * 32;
        cv[r] = __fadd_rn(tv1[ci >> 3], tv2[ci & 7]);
    }
    float fs[5]; int fci[4];
    #pragma unroll
    for (int it = 0; it < 4; it++) {
        float bm; int bi;
        if (cv[0] >= cv[1]) { bm = cv[0]; bi = lane; }
        else                { bm = cv[1]; bi = lane + 32; }
        #pragma unroll
        for (int off = 16; off > 0; off >>= 1) {
            float om = __shfl_xor_sync(0xffffffffu, bm, off);
            int   oi = __shfl_xor_sync(0xffffffffu, bi, off);
            if (om > bm || (om == bm && oi < bi)) { bm = om; bi = oi; }
        }
        fs[it] = bm; fci[it] = bi;
        if ((bi & 31) == lane) cv[bi >> 5] = NEG_BIG;
    }
    if (flag) {
        float m5 = fmaxf(cv[0], cv[1]);
        #pragma unroll
        for (int off = 16; off > 0; off >>= 1)
            m5 = fmaxf(m5, __shfl_xor_sync(0xffffffffu, m5, off));
        fs[4] = m5;
    }

    if (lane == 0) {
        float m = fs[0];
        float e[4], sum = 0.0f;
        #pragma unroll
        for (int k = 0; k < 4; k++) { e[k] = expf(fs[k] - m); sum += e[k]; }
        float* out_scores  = out;
        float* out_experts = out + (size_t)N_TOK * H_HEADS * TOPK;
        #pragma unroll
        for (int k = 0; k < 4; k++) {
            int ci = fci[k];
            int i1 = ti1[ci >> 3];
            int i2 = ti2[ci & 7];
            out_scores [(size_t)gw * TOPK + k] = e[k] / sum;
            out_experts[(size_t)gw * TOPK + k] = (float)(i1 * S_KEYS + i2);
        }
        if (flag) {
            float mg = 1e30f;
            #pragma unroll
            for (int i = 0; i < 7; i++) {
                mg = fminf(mg, tv1[i] - tv1[i + 1]);
                mg = fminf(mg, tv2[i] - tv2[i + 1]);
            }
            mg = fminf(mg, tv1[7] - v9a);
            mg = fminf(mg, tv2[7] - v9b);
            #pragma unroll
            for (int i = 0; i < 4; i++) mg = fminf(mg, fs[i] - fs[i + 1]);
            if (mg < DELTA) {
                int idx = atomicAdd(&g_cnt, 1);
                if (idx < N_TOK * H_HEADS) g_list[idx] = gw;
            }
        }
    }
}

__global__ __launch_bounds__(256) void k_topk_p1(float* __restrict__ out)
{
    int gw   = (blockIdx.x * blockDim.x + threadIdx.x) >> 5;
    int lane = threadIdx.x & 31;
    if (gw >= N_TOK * H_HEADS) return;
    topk_row(gw, lane, out, true);
}

// =====================================================================
// Refine: recompute flagged rows with bitwise-frozen R7 arithmetic.
// =====================================================================
__global__ __launch_bounds__(256) void k_refine(
    const float* __restrict__ x, const float* __restrict__ Wq, const float* __restrict__ bq,
    const float* __restrict__ gamma, const float* __restrict__ beta)
{
    if ((int)blockIdx.x >= g_cnt) return;
    int gw = g_list[blockIdx.x];
    int n = gw >> 2, h = gw & 3;
    int tid = threadIdx.x;

    __shared__ float xs[D_MODEL];
    __shared__ float qh[Q_DIM];
    for (int i = tid; i < D_MODEL; i += 256) xs[i] = x[(size_t)n * D_MODEL + i];
    __syncthreads();

    #pragma unroll
    for (int o = 0; o < 2; o++) {
        int c = tid + o * 256;
        const float* wp = Wq + (size_t)h * D_MODEL * Q_DIM + c;
        float acc = 0.0f;
        #pragma unroll 8
        for (int k = 0; k < D_MODEL; k++)
            acc = fmaf(xs[k], wp[(size_t)k * Q_DIM], acc);
        float qv = acc + bq[h * Q_DIM + c];
        int col = h * Q_DIM + c;
        qh[c] = __fmul_rn(__fsub_rn(qv, g_mun[col]), g_rn[col]) * gamma[col] + beta[col];
    }
    __syncthreads();

    #pragma unroll
    for (int tbl = 0; tbl < 2; tbl++) {
        int j = tid;
        const float* kt = g_Kt + tbl * (HALF * S_KEYS) + j;
        const float* qq = qh + tbl * HALF;
        float acc = 0.0f;
        #pragma unroll 8
        for (int c = 0; c < HALF; c++)
            acc = fmaf(qq[c], kt[c * S_KEYS], acc);
        g_s[(size_t)n * HQ + h * Q_DIM + tbl * HALF + j] = acc;
    }
}

__global__ __launch_bounds__(256) void k_topk_p2(float* __restrict__ out)
{
    int wi   = (blockIdx.x * blockDim.x + threadIdx.x) >> 5;
    int lane = threadIdx.x & 31;
    if (wi >= g_cnt) return;
    topk_row(g_list[wi], lane, out, false);
}

// -------------------- launch --------------------
extern "C" void kernel_launch(void* const* d_in, const int* in_sizes, int n_in,
                              void* d_out, int out_size)
{
    const float* x     = (const float*)d_in[0];
    const float* Wq    = (const float*)d_in[1];
    const float* bq    = (const float*)d_in[2];
    const float* gamma = (const float*)d_in[3];
    const float* beta  = (const float*)d_in[4];
    const float* K1    = (const float*)d_in[5];
    const float* K2    = (const float*)d_in[6];
    float* out = (float*)d_out;

    cudaFuncSetAttribute(k_gemm_q_mma, cudaFuncAttributeMaxDynamicSharedMemorySize, SMEM_MMA);

    k_split_x<<<(N_TOK * D_MODEL) / (256 * 4), 256>>>(x);
    k_split_w<<<dim3(D_MODEL / 32, Q_DIM / 32, H_HEADS), dim3(32, 8)>>>(Wq);
    k_gemm_q_mma<<<dim3(HQ / 64, N_TOK / 128), 256, SMEM_MMA>>>(bq);
    k_mean_part<<<dim3(256, NPART), 256>>>();
    k_mean_fin<<<8, 256>>>();
    k_var_part<<<dim3(256, NPART), 256>>>();
    k_var_fin<<<8, 256>>>();
    k_transpose<<<512, 256>>>(K1, K2);
    k_gemm_s<<<dim3(128, 2, 8), 512>>>(gamma, beta);
    k_topk_p1<<<(N_TOK * H_HEADS * 32) / 256, 256>>>(out);
    k_refine<<<N_TOK * H_HEADS, 256>>>(x, Wq, bq, gamma, beta);
    k_topk_p2<<<(N_TOK * H_HEADS) / 8, 256>>>(out);
}

// round 17
// speedup vs baseline: 1.7149x; 1.3210x over previous
#include <cuda_runtime.h>
#include <cuda_fp16.h>
#include <math.h>

#define N_TOK   16384
#define D_MODEL 2048
#define Q_DIM   512
#define H_HEADS 4
#define HQ      2048      // H * Q
#define HALF    256       // Q/2
#define S_KEYS  256
#define TOPK    4
#define BN_EPS  1e-5f
#define NEG_BIG (-1e30f)
#define NPART   4
#define CHUNK   (N_TOK / NPART)
#define DELTA   1e-4f     // suspicion margin (>> mma-path noise)

typedef unsigned long long u64;
typedef unsigned int u32;

// -------------------- device scratch (static, no allocation) --------------------
static __device__ float  g_q [(size_t)N_TOK * HQ];
static __device__ float  g_s [(size_t)N_TOK * HQ];
static __device__ float  g_pm[NPART][HQ];
static __device__ float  g_pv[NPART][HQ];
static __device__ float  g_mun[HQ];
static __device__ float  g_rn [HQ];
static __device__ float  g_Kt [2 * HALF * S_KEYS];
static __device__ int    g_cnt;
static __device__ int    g_list[N_TOK * H_HEADS];
// fp16 2-way splits of x (A) and transposed Wq (B, [h*512+n][k])
static __device__ __align__(16) __half g_xs1[(size_t)N_TOK * D_MODEL];
static __device__ __align__(16) __half g_xs2[(size_t)N_TOK * D_MODEL];
static __device__ __align__(16) __half g_ws1[(size_t)HQ * D_MODEL];
static __device__ __align__(16) __half g_ws2[(size_t)HQ * D_MODEL];

// -------------------- helpers --------------------
__device__ __forceinline__ u32 smem_u32(const void* p) {
    u32 a;
    asm("{ .reg .u64 t; cvta.to.shared.u64 t, %1; cvt.u32.u64 %0, t; }" : "=r"(a) : "l"(p));
    return a;
}
__device__ __forceinline__ u64 f2_pack(float lo, float hi) {
    u64 r; asm("mov.b64 %0, {%1, %2};" : "=l"(r) : "f"(lo), "f"(hi)); return r;
}
__device__ __forceinline__ void f2_unpack(u64 v, float& lo, float& hi) {
    asm("mov.b64 {%0, %1}, %2;" : "=f"(lo), "=f"(hi) : "l"(v));
}
__device__ __forceinline__ u64 f2_fma(u64 a, u64 b, u64 c) {
    u64 d; asm("fma.rn.f32x2 %0, %1, %2, %3;" : "=l"(d) : "l"(a), "l"(b), "l"(c)); return d;
}
__device__ __forceinline__ void mma_f16(float* d, const u32* a, const u32* b) {
    asm volatile(
        "mma.sync.aligned.m16n8k16.row.col.f32.f16.f16.f32 "
        "{%0,%1,%2,%3}, {%4,%5,%6,%7}, {%8,%9}, {%0,%1,%2,%3};"
        : "+f"(d[0]), "+f"(d[1]), "+f"(d[2]), "+f"(d[3])
        : "r"(a[0]), "r"(a[1]), "r"(a[2]), "r"(a[3]), "r"(b[0]), "r"(b[1]));
}
__device__ __forceinline__ void ldsm_x4(u32& r0, u32& r1, u32& r2, u32& r3, u32 addr) {
    asm volatile("ldmatrix.sync.aligned.m8n8.x4.shared.b16 {%0,%1,%2,%3}, [%4];"
                 : "=r"(r0), "=r"(r1), "=r"(r2), "=r"(r3) : "r"(addr));
}
#define CP_ASYNC16(dst, src) \
    asm volatile("cp.async.cg.shared.global [%0], [%1], 16;" :: "r"(dst), "l"(src))

// =====================================================================
// Split kernels: fp16 2-way. v = s1 + s2 + O(2^-22 v)
// =====================================================================
__device__ __forceinline__ void split2(float v, __half& h1, __half& h2) {
    h1 = __float2half_rn(v);
    h2 = __float2half_rn(v - __half2float(h1));
}

__global__ __launch_bounds__(256) void k_split_x(const float* __restrict__ x)
{
    if (blockIdx.x == 0 && threadIdx.x == 0) g_cnt = 0;
    size_t i0 = ((size_t)blockIdx.x * 256 + threadIdx.x) * 4;
    float4 v = *(const float4*)(x + i0);
    float vv[4] = {v.x, v.y, v.z, v.w};
    #pragma unroll
    for (int u = 0; u < 4; u++) {
        __half h1, h2;
        split2(vv[u], h1, h2);
        g_xs1[i0 + u] = h1; g_xs2[i0 + u] = h2;
    }
}

__global__ void k_split_w(const float* __restrict__ Wq)
{
    __shared__ float tile[32][33];
    int k0 = blockIdx.x * 32, n0 = blockIdx.y * 32, h = blockIdx.z;
    int tx = threadIdx.x, ty = threadIdx.y;
    #pragma unroll
    for (int q = 0; q < 4; q++) {
        int r = ty + q * 8;
        tile[r][tx] = Wq[(size_t)h * D_MODEL * Q_DIM + (size_t)(k0 + r) * Q_DIM + n0 + tx];
    }
    __syncthreads();
    #pragma unroll
    for (int q = 0; q < 4; q++) {
        int nn = ty + q * 8;
        float v = tile[tx][nn];
        __half h1, h2;
        split2(v, h1, h2);
        size_t o = (size_t)(h * Q_DIM + n0 + nn) * D_MODEL + k0 + tx;
        g_ws1[o] = h1; g_ws2[o] = h2;
    }
}

// =====================================================================
// Kernel 1: q = x @ Wq + bq via mma.sync m16n8k16 fp16, 2-split/3-product.
// hi = s1*s1 (full magnitude); lo = s1*s2 + s2*s1 (<=2^-11 scale).
// q = (hi + lo) + bias. Deterministic product order (0,0),(0,1),(1,0).
// Perf scheme carried from R16: colTile-fast grid, ldmatrix.x4, 2-stage
// cp.async double buffering, occupancy 2.
// Block 128x64, BK=32, 256 thr = 8 warps (4m x 2n), warp tile 32x32.
// =====================================================================
#define RSB      80
#define ASM_OFF(s) ((s) * 10240)                  // A: 128 rows * 80B, 2 splits
#define BSM_OFF(s) (20480 + (s) * 5120)           // B: 64 rows * 80B, 2 splits
#define STAGE_B  30720
#define SMEM_MMA (2 * STAGE_B)                    // 61440

__global__ __launch_bounds__(256, 2) void k_gemm_q_mma(const float* __restrict__ bq)
{
    extern __shared__ char smem[];
    const u32 sbase = smem_u32(smem);
    const int tid  = threadIdx.x;
    const int wid  = tid >> 5, lane = tid & 31;
    const int m0   = (wid & 3) * 32;
    const int n0   = (wid >> 2) * 32;
    const int col0 = blockIdx.x * 64;       // colTile fast -> A L2-resident
    const int row0 = blockIdx.y * 128;

    float dh[2][4][4], dl[2][4][4];
    #pragma unroll
    for (int mf = 0; mf < 2; mf++)
        #pragma unroll
        for (int nf = 0; nf < 4; nf++)
            #pragma unroll
            for (int e = 0; e < 4; e++) { dh[mf][nf][e] = 0.0f; dl[mf][nf][e] = 0.0f; }

    const int lt = lane >> 3, lrr = lane & 7;
    u32 aRow[2];
    #pragma unroll
    for (int mf = 0; mf < 2; mf++)
        aRow[mf] = sbase + (u32)((m0 + mf * 16 + (lt & 1) * 8 + lrr) * RSB + (lt >> 1) * 16);
    u32 bRow[2];
    #pragma unroll
    for (int np = 0; np < 2; np++)
        bRow[np] = sbase + (u32)(BSM_OFF(0) + (n0 + np * 16 + (lt >> 1) * 8 + lrr) * RSB + (lt & 1) * 16);

    const int ar0 = tid >> 2, ak0 = (tid & 3) * 8;
    const int ar1 = (tid + 256) >> 2, ak1 = ((tid + 256) & 3) * 8;

    // ---- prologue: stage 0 ----
    #pragma unroll
    for (int s = 0; s < 2; s++) {
        const __half* X = (s == 0) ? g_xs1 : g_xs2;
        const __half* W = (s == 0) ? g_ws1 : g_ws2;
        CP_ASYNC16(sbase + ASM_OFF(s) + ar0 * RSB + ak0 * 2,
                   X + (size_t)(row0 + ar0) * D_MODEL + ak0);
        CP_ASYNC16(sbase + ASM_OFF(s) + ar1 * RSB + ak1 * 2,
                   X + (size_t)(row0 + ar1) * D_MODEL + ak1);
        CP_ASYNC16(sbase + BSM_OFF(s) + ar0 * RSB + ak0 * 2,
                   W + (size_t)(col0 + ar0) * D_MODEL + ak0);
    }
    asm volatile("cp.async.commit_group;");

    for (int kt = 0; kt < D_MODEL; kt += 32) {
        const u32 stoff = (u32)(((kt >> 5) & 1) * STAGE_B);
        const int ktn = kt + 32;
        if (ktn < D_MODEL) {
            const u32 nstoff = (u32)(((ktn >> 5) & 1) * STAGE_B);
            #pragma unroll
            for (int s = 0; s < 2; s++) {
                const __half* X = (s == 0) ? g_xs1 : g_xs2;
                const __half* W = (s == 0) ? g_ws1 : g_ws2;
                CP_ASYNC16(sbase + nstoff + ASM_OFF(s) + ar0 * RSB + ak0 * 2,
                           X + (size_t)(row0 + ar0) * D_MODEL + ktn + ak0);
                CP_ASYNC16(sbase + nstoff + ASM_OFF(s) + ar1 * RSB + ak1 * 2,
                           X + (size_t)(row0 + ar1) * D_MODEL + ktn + ak1);
                CP_ASYNC16(sbase + nstoff + BSM_OFF(s) + ar0 * RSB + ak0 * 2,
                           W + (size_t)(col0 + ar0) * D_MODEL + ktn + ak0);
            }
            asm volatile("cp.async.commit_group;");
            asm volatile("cp.async.wait_group 1;");
        } else {
            asm volatile("cp.async.wait_group 0;");
        }
        __syncthreads();

        #pragma unroll
        for (int ks = 0; ks < 2; ks++) {
            const u32 ko = stoff + ks * 32;
            u32 bfr[2][4][2];
            #pragma unroll
            for (int sj = 0; sj < 2; sj++)
                #pragma unroll
                for (int np = 0; np < 2; np++)
                    ldsm_x4(bfr[sj][2 * np][0], bfr[sj][2 * np][1],
                            bfr[sj][2 * np + 1][0], bfr[sj][2 * np + 1][1],
                            bRow[np] + sj * 5120 + ko);
            u32 afr[2][2][4];
            #pragma unroll
            for (int si = 0; si < 2; si++)
                #pragma unroll
                for (int mf = 0; mf < 2; mf++)
                    ldsm_x4(afr[si][mf][0], afr[si][mf][1], afr[si][mf][2], afr[si][mf][3],
                            aRow[mf] + si * 10240 + ko);
            // product order: (0,0)->hi, (0,1)->lo, (1,0)->lo; nf inner, (mf0,mf1)
            #pragma unroll
            for (int nf = 0; nf < 4; nf++) {
                mma_f16(dh[0][nf], afr[0][0], bfr[0][nf]);
                mma_f16(dh[1][nf], afr[0][1], bfr[0][nf]);
            }
            #pragma unroll
            for (int nf = 0; nf < 4; nf++) {
                mma_f16(dl[0][nf], afr[0][0], bfr[1][nf]);
                mma_f16(dl[1][nf], afr[0][1], bfr[1][nf]);
            }
            #pragma unroll
            for (int nf = 0; nf < 4; nf++) {
                mma_f16(dl[0][nf], afr[1][0], bfr[0][nf]);
                mma_f16(dl[1][nf], afr[1][1], bfr[0][nf]);
            }
        }
        __syncthreads();
    }

    const int lr = lane >> 2;
    const int lk = (lane & 3) * 2;
    #pragma unroll
    for (int mf = 0; mf < 2; mf++) {
        #pragma unroll
        for (int nf = 0; nf < 4; nf++) {
            int r = row0 + m0 + mf * 16 + lr;
            int c = col0 + n0 + nf * 8 + lk;
            g_q[(size_t)r * HQ + c]           = (dh[mf][nf][0] + dl[mf][nf][0]) + bq[c];
            g_q[(size_t)r * HQ + c + 1]       = (dh[mf][nf][1] + dl[mf][nf][1]) + bq[c + 1];
            g_q[(size_t)(r + 8) * HQ + c]     = (dh[mf][nf][2] + dl[mf][nf][2]) + bq[c];
            g_q[(size_t)(r + 8) * HQ + c + 1] = (dh[mf][nf][3] + dl[mf][nf][3]) + bq[c + 1];
        }
    }
}

// =====================================================================
// Stats (frozen recipe, MLP-8 loads).
// =====================================================================
__global__ __launch_bounds__(256) void k_mean_part()
{
    int c    = blockIdx.x * 8 + (threadIdx.x >> 5);
    int b    = blockIdx.y;
    int lane = threadIdx.x & 31;
    float s = 0.0f;
    const float* p = g_q + ((size_t)b * CHUNK + lane) * HQ + c;
    #pragma unroll 1
    for (int j = 0; j < CHUNK / 32; j += 8) {
        float v[8];
        #pragma unroll
        for (int u = 0; u < 8; u++) v[u] = p[(size_t)(j + u) * 32 * HQ];
        #pragma unroll
        for (int u = 0; u < 8; u++) s = __fadd_rn(s, v[u]);
    }
    #pragma unroll
    for (int off = 16; off > 0; off >>= 1)
        s = __fadd_rn(s, __shfl_down_sync(0xffffffffu, s, off));
    if (lane == 0) g_pm[b][c] = s;
}

__global__ __launch_bounds__(256) void k_mean_fin()
{
    int c = blockIdx.x * 256 + threadIdx.x;
    float s = g_pm[0][c];
    #pragma unroll
    for (int b = 1; b < NPART; b++) s = __fadd_rn(s, g_pm[b][c]);
    g_mun[c] = s * (1.0f / (float)N_TOK);
}

__global__ __launch_bounds__(256) void k_var_part()
{
    int c    = blockIdx.x * 8 + (threadIdx.x >> 5);
    int b    = blockIdx.y;
    int lane = threadIdx.x & 31;
    float mu = g_mun[c];
    float s = 0.0f;
    const float* p = g_q + ((size_t)b * CHUNK + lane) * HQ + c;
    #pragma unroll 1
    for (int j = 0; j < CHUNK / 32; j += 8) {
        float v[8];
        #pragma unroll
        for (int u = 0; u < 8; u++) v[u] = p[(size_t)(j + u) * 32 * HQ];
        #pragma unroll
        for (int u = 0; u < 8; u++) {
            float dd = __fsub_rn(v[u], mu);
            s = __fadd_rn(s, __fmul_rn(dd, dd));
        }
    }
    #pragma unroll
    for (int off = 16; off > 0; off >>= 1)
        s = __fadd_rn(s, __shfl_down_sync(0xffffffffu, s, off));
    if (lane == 0) g_pv[b][c] = s;
}

__global__ __launch_bounds__(256) void k_var_fin()
{
    int c = blockIdx.x * 256 + threadIdx.x;
    float s = g_pv[0][c];
    #pragma unroll
    for (int b = 1; b < NPART; b++) s = __fadd_rn(s, g_pv[b][c]);
    float var = s * (1.0f / (float)N_TOK);
    g_rn[c] = rsqrtf(__fadd_rn(var, BN_EPS));
}

__global__ __launch_bounds__(256) void k_transpose(
    const float* __restrict__ K1, const float* __restrict__ K2)
{
    int idx = blockIdx.x * 256 + threadIdx.x;
    int tbl = idx >> 16;
    int c   = (idx >> 8) & 255;
    int k   = idx & 255;
    const float* Ksrc = tbl ? K2 : K1;
    g_Kt[idx] = Ksrc[k * HALF + c];
}

// =====================================================================
// Kernel 4: scoring GEMM (frozen recipe) on mma-q.
// =====================================================================
__global__ __launch_bounds__(512) void k_gemm_s(
    const float* __restrict__ gamma, const float* __restrict__ beta)
{
    __shared__ float As[16][128];
    __shared__ float Bs[16][128];

    const int tid = threadIdx.x;
    const int tx  = tid & 15;
    const int ty  = tid >> 4;

    const int z   = blockIdx.z;
    const int tbl = z >> 2;
    const int h   = z & 3;
    const int cb  = h * Q_DIM + tbl * HALF;

    const float* A  = g_q + (size_t)blockIdx.x * 128 * HQ + cb;
    const float* B  = g_Kt + (size_t)tbl * HALF * S_KEYS + blockIdx.y * 128;
    const float* mu = g_mun + cb;
    const float* rn = g_rn  + cb;
    const float* gm = gamma + cb;
    const float* bt = beta  + cb;

    u64 acc2[4][4];
    #pragma unroll
    for (int i = 0; i < 4; i++)
        #pragma unroll
        for (int m = 0; m < 4; m++) acc2[i][m] = 0ull;

    const int ar = tid >> 2;
    const int ac = (tid & 3) * 4;
    const int br = tid >> 5;
    const int bc = (tid & 31) * 4;

    for (int kt = 0; kt < HALF; kt += 16) {
        float4 va = *(const float4*)(A + (size_t)ar * HQ + kt + ac);
        int c0 = kt + ac;
        va.x = __fmul_rn(__fsub_rn(va.x, mu[c0 + 0]), rn[c0 + 0]) * gm[c0 + 0] + bt[c0 + 0];
        va.y = __fmul_rn(__fsub_rn(va.y, mu[c0 + 1]), rn[c0 + 1]) * gm[c0 + 1] + bt[c0 + 1];
        va.z = __fmul_rn(__fsub_rn(va.z, mu[c0 + 2]), rn[c0 + 2]) * gm[c0 + 2] + bt[c0 + 2];
        va.w = __fmul_rn(__fsub_rn(va.w, mu[c0 + 3]), rn[c0 + 3]) * gm[c0 + 3] + bt[c0 + 3];
        As[ac + 0][ar] = va.x; As[ac + 1][ar] = va.y;
        As[ac + 2][ar] = va.z; As[ac + 3][ar] = va.w;
        *(float4*)(&Bs[br][bc]) = *(const float4*)(B + (size_t)(kt + br) * S_KEYS + bc);
        __syncthreads();

        #pragma unroll
        for (int k = 0; k < 16; k++) {
            u64 a2[4], b2[4];
            #pragma unroll
            for (int i = 0; i < 4; i++) {
                float av = As[k][ty * 4 + i];
                a2[i] = f2_pack(av, av);
            }
            #pragma unroll
            for (int m = 0; m < 4; m++)
                b2[m] = *(const u64*)(&Bs[k][tx * 8 + m * 2]);
            #pragma unroll
            for (int i = 0; i < 4; i++)
                #pragma unroll
                for (int m = 0; m < 4; m++)
                    acc2[i][m] = f2_fma(a2[i], b2[m], acc2[i][m]);
        }
        __syncthreads();
    }

    float* C = g_s + (size_t)blockIdx.x * 128 * HQ + cb + blockIdx.y * 128;
    #pragma unroll
    for (int i = 0; i < 4; i++) {
        int r = ty * 4 + i;
        #pragma unroll
        for (int m = 0; m < 4; m++) {
            float lo, hi;
            f2_unpack(acc2[i][m], lo, hi);
            int c = tx * 8 + m * 2;
            C[(size_t)r * HQ + c + 0] = lo;
            C[(size_t)r * HQ + c + 1] = hi;
        }
    }
}

// =====================================================================
// Shared top-k device function (frozen algorithm).
// =====================================================================
__device__ __forceinline__ void topk_row(int gw, int lane, float* out, bool flag)
{
    int n = gw >> 2;
    int h = gw & 3;

    const float* s1 = g_s + (size_t)n * HQ + h * Q_DIM;
    const float* s2 = s1 + HALF;

    float v1[8], v2[8];
    #pragma unroll
    for (int t = 0; t < 8; t++) { v1[t] = s1[t * 32 + lane]; v2[t] = s2[t * 32 + lane]; }

    float tv1[8], tv2[8];
    int   ti1[8], ti2[8];

    #pragma unroll
    for (int it = 0; it < 8; it++) {
        float bm = NEG_BIG; int bi = 0x7fffffff;
        #pragma unroll
        for (int t = 0; t < 8; t++)
            if (v1[t] > bm) { bm = v1[t]; bi = t * 32 + lane; }
        #pragma unroll
        for (int off = 16; off > 0; off >>= 1) {
            float om = __shfl_xor_sync(0xffffffffu, bm, off);
            int   oi = __shfl_xor_sync(0xffffffffu, bi, off);
            if (om > bm || (om == bm && oi < bi)) { bm = om; bi = oi; }
        }
        tv1[it] = bm; ti1[it] = bi;
        if ((bi & 31) == lane) v1[bi >> 5] = NEG_BIG;
    }
    #pragma unroll
    for (int it = 0; it < 8; it++) {
        float bm = NEG_BIG; int bi = 0x7fffffff;
        #pragma unroll
        for (int t = 0; t < 8; t++)
            if (v2[t] > bm) { bm = v2[t]; bi = t * 32 + lane; }
        #pragma unroll
        for (int off = 16; off > 0; off >>= 1) {
            float om = __shfl_xor_sync(0xffffffffu, bm, off);
            int   oi = __shfl_xor_sync(0xffffffffu, bi, off);
            if (om > bm || (om == bm && oi < bi)) { bm = om; bi = oi; }
        }
        tv2[it] = bm; ti2[it] = bi;
        if ((bi & 31) == lane) v2[bi >> 5] = NEG_BIG;
    }

    float v9a = NEG_BIG, v9b = NEG_BIG;
    if (flag) {
        #pragma unroll
        for (int t = 0; t < 8; t++) { v9a = fmaxf(v9a, v1[t]); v9b = fmaxf(v9b, v2[t]); }
        #pragma unroll
        for (int off = 16; off > 0; off >>= 1) {
            v9a = fmaxf(v9a, __shfl_xor_sync(0xffffffffu, v9a, off));
            v9b = fmaxf(v9b, __shfl_xor_sync(0xffffffffu, v9b, off));
        }
    }

    float cv[2];
    #pragma unroll
    for (int r = 0; r < 2; r++) {
        int ci = lane + r * 32;
        cv[r] = __fadd_rn(tv1[ci >> 3], tv2[ci & 7]);
    }
    float fs[5]; int fci[4];
    #pragma unroll
    for (int it = 0; it < 4; it++) {
        float bm; int bi;
        if (cv[0] >= cv[1]) { bm = cv[0]; bi = lane; }
        else                { bm = cv[1]; bi = lane + 32; }
        #pragma unroll
        for (int off = 16; off > 0; off >>= 1) {
            float om = __shfl_xor_sync(0xffffffffu, bm, off);
            int   oi = __shfl_xor_sync(0xffffffffu, bi, off);
            if (om > bm || (om == bm && oi < bi)) { bm = om; bi = oi; }
        }
        fs[it] = bm; fci[it] = bi;
        if ((bi & 31) == lane) cv[bi >> 5] = NEG_BIG;
    }
    if (flag) {
        float m5 = fmaxf(cv[0], cv[1]);
        #pragma unroll
        for (int off = 16; off > 0; off >>= 1)
            m5 = fmaxf(m5, __shfl_xor_sync(0xffffffffu, m5, off));
        fs[4] = m5;
    }

    if (lane == 0) {
        float m = fs[0];
        float e[4], sum = 0.0f;
        #pragma unroll
        for (int k = 0; k < 4; k++) { e[k] = expf(fs[k] - m); sum += e[k]; }
        float* out_scores  = out;
        float* out_experts = out + (size_t)N_TOK * H_HEADS * TOPK;
        #pragma unroll
        for (int k = 0; k < 4; k++) {
            int ci = fci[k];
            int i1 = ti1[ci >> 3];
            int i2 = ti2[ci & 7];
            out_scores [(size_t)gw * TOPK + k] = e[k] / sum;
            out_experts[(size_t)gw * TOPK + k] = (float)(i1 * S_KEYS + i2);
        }
        if (flag) {
            float mg = 1e30f;
            #pragma unroll
            for (int i = 0; i < 7; i++) {
                mg = fminf(mg, tv1[i] - tv1[i + 1]);
                mg = fminf(mg, tv2[i] - tv2[i + 1]);
            }
            mg = fminf(mg, tv1[7] - v9a);
            mg = fminf(mg, tv2[7] - v9b);
            #pragma unroll
            for (int i = 0; i < 4; i++) mg = fminf(mg, fs[i] - fs[i + 1]);
            if (mg < DELTA) {
                int idx = atomicAdd(&g_cnt, 1);
                if (idx < N_TOK * H_HEADS) g_list[idx] = gw;
            }
        }
    }
}

__global__ __launch_bounds__(256) void k_topk_p1(float* __restrict__ out)
{
    int gw   = (blockIdx.x * blockDim.x + threadIdx.x) >> 5;
    int lane = threadIdx.x & 31;
    if (gw >= N_TOK * H_HEADS) return;
    topk_row(gw, lane, out, true);
}

// =====================================================================
// Refine: recompute flagged rows with bitwise-frozen R7 arithmetic.
// =====================================================================
__global__ __launch_bounds__(256) void k_refine(
    const float* __restrict__ x, const float* __restrict__ Wq, const float* __restrict__ bq,
    const float* __restrict__ gamma, const float* __restrict__ beta)
{
    if ((int)blockIdx.x >= g_cnt) return;
    int gw = g_list[blockIdx.x];
    int n = gw >> 2, h = gw & 3;
    int tid = threadIdx.x;

    __shared__ float xs[D_MODEL];
    __shared__ float qh[Q_DIM];
    for (int i = tid; i < D_MODEL; i += 256) xs[i] = x[(size_t)n * D_MODEL + i];
    __syncthreads();

    #pragma unroll
    for (int o = 0; o < 2; o++) {
        int c = tid + o * 256;
        const float* wp = Wq + (size_t)h * D_MODEL * Q_DIM + c;
        float acc = 0.0f;
        #pragma unroll 8
        for (int k = 0; k < D_MODEL; k++)
            acc = fmaf(xs[k], wp[(size_t)k * Q_DIM], acc);
        float qv = acc + bq[h * Q_DIM + c];
        int col = h * Q_DIM + c;
        qh[c] = __fmul_rn(__fsub_rn(qv, g_mun[col]), g_rn[col]) * gamma[col] + beta[col];
    }
    __syncthreads();

    #pragma unroll
    for (int tbl = 0; tbl < 2; tbl++) {
        int j = tid;
        const float* kt = g_Kt + tbl * (HALF * S_KEYS) + j;
        const float* qq = qh + tbl * HALF;
        float acc = 0.0f;
        #pragma unroll 8
        for (int c = 0; c < HALF; c++)
            acc = fmaf(qq[c], kt[c * S_KEYS], acc);
        g_s[(size_t)n * HQ + h * Q_DIM + tbl * HALF + j] = acc;
    }
}

__global__ __launch_bounds__(256) void k_topk_p2(float* __restrict__ out)
{
    int wi   = (blockIdx.x * blockDim.x + threadIdx.x) >> 5;
    int lane = threadIdx.x & 31;
    if (wi >= g_cnt) return;
    topk_row(g_list[wi], lane, out, false);
}

// -------------------- launch --------------------
extern "C" void kernel_launch(void* const* d_in, const int* in_sizes, int n_in,
                              void* d_out, int out_size)
{
    const float* x     = (const float*)d_in[0];
    const float* Wq    = (const float*)d_in[1];
    const float* bq    = (const float*)d_in[2];
    const float* gamma = (const float*)d_in[3];
    const float* beta  = (const float*)d_in[4];
    const float* K1    = (const float*)d_in[5];
    const float* K2    = (const float*)d_in[6];
    float* out = (float*)d_out;

    cudaFuncSetAttribute(k_gemm_q_mma, cudaFuncAttributeMaxDynamicSharedMemorySize, SMEM_MMA);

    k_split_x<<<(N_TOK * D_MODEL) / (256 * 4), 256>>>(x);
    k_split_w<<<dim3(D_MODEL / 32, Q_DIM / 32, H_HEADS), dim3(32, 8)>>>(Wq);
    k_gemm_q_mma<<<dim3(HQ / 64, N_TOK / 128), 256, SMEM_MMA>>>(bq);
    k_mean_part<<<dim3(256, NPART), 256>>>();
    k_mean_fin<<<8, 256>>>();
    k_var_part<<<dim3(256, NPART), 256>>>();
    k_var_fin<<<8, 256>>>();
    k_transpose<<<512, 256>>>(K1, K2);
    k_gemm_s<<<dim3(128, 2, 8), 512>>>(gamma, beta);
    k_topk_p1<<<(N_TOK * H_HEADS * 32) / 256, 256>>>(out);
    k_refine<<<N_TOK * H_HEADS, 256>>>(x, Wq, bq, gamma, beta);
    k_topk_p2<<<(N_TOK * H_HEADS) / 8, 256>>>(out);
}